// round 9
// baseline (speedup 1.0000x reference)
#include <cuda_runtime.h>
#include <stdint.h>
#include <stddef.h>

#define D 256
#define LMAX 100000
#define CMAX 50000

// ---- scratch (device globals: allocation-free per harness rules) ----
__device__ float g_hid  [(size_t)LMAX * D];
__device__ float g_lfeat[(size_t)LMAX * D];
__device__ float g_l2l  [(size_t)LMAX * D];
__device__ float g_laggr[(size_t)LMAX * D];
__device__ float g_cfeat[(size_t)CMAX * D];
__device__ float g_caggr[(size_t)CMAX * D];

// ---- base-target PTX helpers (sm_80/sm_90/sm_100 base; NO "a" features) ----
__device__ __forceinline__ uint32_t smem_u32(const void* p) {
    uint32_t a;
    asm("{ .reg .u64 t; cvta.to.shared.u64 t, %1; cvt.u32.u64 %0, t; }" : "=r"(a) : "l"(p));
    return a;
}
__device__ __forceinline__ void cp_async16(uint32_t dst, const void* src) {
    asm volatile("cp.async.cg.shared.global [%0], [%1], 16;" :: "r"(dst), "l"(src));
}
#define CP_ASYNC_COMMIT() asm volatile("cp.async.commit_group;" ::: "memory")
#define CP_ASYNC_WAIT0()  asm volatile("cp.async.wait_group 0;" ::: "memory")

__device__ __forceinline__ void fma_x2(unsigned long long& d,
                                       unsigned long long a, unsigned long long b) {
    asm("fma.rn.f32x2 %0, %1, %2, %0;" : "+l"(d) : "l"(a), "l"(b));
}

// ============================================================================
// Fused GEMM: Out[M,256] = act( sum_s A_s[M,256] @ W[s*256:(s+1)*256,:] + bias )
// fp32 math via packed fma.rn.f32x2. BM=128,BN=128,BK=16, 256 threads,
// 8x8 microtile (stored as 8x4 packed pairs). Double-buffered SMEM:
// A fp32 loaded->regs->stored DUPLICATED ({a,a} pairs) so packed multiplicands
// come straight from LDS.128; B tile via cp.async.
// ============================================================================
#define BM 128
#define BN 128
#define BK 16
#define ASD_OFF 0          // duplicated A: BK x (2*BM) floats = 16 KB
#define BS_OFF  16384      // B: BK x BN floats = 8 KB
#define STAGE_BYTES 24576
#define SMEM_REQ (2 * STAGE_BYTES)

__global__ __launch_bounds__(256, 2) void gemm_f32x2(
    const float* __restrict__ A0, const float* __restrict__ A1,
    const float* __restrict__ A2,
    const float* __restrict__ W,      // [nseg*256, 256] row-major
    const float* __restrict__ bias,   // [256]
    float* __restrict__ Out,          // [M, 256]
    int M, int nseg, int swap0, int relu)
{
    extern __shared__ char sm[];
    const uint32_t smb = smem_u32(sm);
    const int tid = threadIdx.x;
    const int block_row = blockIdx.y * BM;
    const int block_col = blockIdx.x * BN;
    const int ty = tid >> 4;          // 0..15
    const int tx = tid & 15;          // 0..15

    const float* Aseg[3] = {A0, A1, A2};
    const int T = nseg * (D / BK);    // 16/32/48 k-tiles

    unsigned long long acc[8][4];
    #pragma unroll
    for (int i = 0; i < 8; i++)
        #pragma unroll
        for (int j = 0; j < 4; j++) acc[i][j] = 0ULL;

    // per-thread load coords
    const int a_r0 = tid >> 2;              // 0..63  (it adds +64)
    const int a_kq = (tid & 3) * 4;         // 0,4,8,12
    const int b_k0 = tid >> 5;              // 0..7   (it adds +8)
    const int b_nq = (tid & 31) * 4;        // 0..124

    float4 pref[2];

    // ---- prologue: tile 0 ----
    {
        const float* A = Aseg[0];
        const bool swap = (swap0 != 0);
        #pragma unroll
        for (int it = 0; it < 2; it++) {
            int r = a_r0 + it * 64;
            int row = block_row + r;
            float4 v = make_float4(0.f, 0.f, 0.f, 0.f);
            if (row < M) {
                int ar = swap ? (row ^ 1) : row;
                v = *reinterpret_cast<const float4*>(A + (size_t)ar * D + a_kq);
            }
            float vv[4] = {v.x, v.y, v.z, v.w};
            #pragma unroll
            for (int j = 0; j < 4; j++) {
                float2* p = reinterpret_cast<float2*>(
                    sm + ASD_OFF + ((a_kq + j) * 2 * BM + 2 * r) * 4);
                *p = make_float2(vv[j], vv[j]);
            }
        }
        #pragma unroll
        for (int it = 0; it < 2; it++) {
            int k = b_k0 + it * 8;
            cp_async16(smb + BS_OFF + (uint32_t)(k * BN + b_nq) * 4,
                       W + (size_t)k * D + block_col + b_nq);
        }
        CP_ASYNC_COMMIT();
        CP_ASYNC_WAIT0();
        __syncthreads();
    }

    for (int t = 0; t < T; t++) {
        const uint32_t st  = smb + (uint32_t)(t & 1) * STAGE_BYTES;
        const char*    stc = sm + (size_t)(t & 1) * STAGE_BYTES;
        const uint32_t nst = smb + (uint32_t)((t + 1) & 1) * STAGE_BYTES;
        char*          nstc = sm + (size_t)((t + 1) & 1) * STAGE_BYTES;
        const bool have_next = (t + 1 < T);

        // issue next tile's loads: A -> regs (LDG), B -> smem (cp.async)
        if (have_next) {
            int tn = t + 1;
            int s = tn >> 4;
            int klocal = (tn & 15) * BK;
            const float* A = Aseg[s];
            const bool swap = (s == 0) && swap0;
            #pragma unroll
            for (int it = 0; it < 2; it++) {
                int r = a_r0 + it * 64;
                int row = block_row + r;
                float4 v = make_float4(0.f, 0.f, 0.f, 0.f);
                if (row < M) {
                    int ar = swap ? (row ^ 1) : row;
                    v = *reinterpret_cast<const float4*>(
                        A + (size_t)ar * D + klocal + a_kq);
                }
                pref[it] = v;
            }
            const float* Wt = W + (size_t)(s * D + klocal) * D;
            #pragma unroll
            for (int it = 0; it < 2; it++) {
                int k = b_k0 + it * 8;
                cp_async16(nst + BS_OFF + (uint32_t)(k * BN + b_nq) * 4,
                           Wt + (size_t)k * D + block_col + b_nq);
            }
            CP_ASYNC_COMMIT();
        }

        // ---- compute current tile ----
        #pragma unroll
        for (int k = 0; k < BK; k++) {
            unsigned long long a2[8], b2[4];
            #pragma unroll
            for (int i = 0; i < 4; i++) {
                ulonglong2 q = *reinterpret_cast<const ulonglong2*>(
                    stc + ASD_OFF + (k * 2 * BM + ty * 16 + i * 4) * 4);
                a2[2 * i]     = q.x;
                a2[2 * i + 1] = q.y;
            }
            #pragma unroll
            for (int i = 0; i < 2; i++) {
                ulonglong2 q = *reinterpret_cast<const ulonglong2*>(
                    stc + BS_OFF + (k * BN + tx * 8 + i * 4) * 4);
                b2[2 * i]     = q.x;
                b2[2 * i + 1] = q.y;
            }
            #pragma unroll
            for (int i = 0; i < 8; i++)
                #pragma unroll
                for (int j = 0; j < 4; j++)
                    fma_x2(acc[i][j], a2[i], b2[j]);
        }

        // publish next tile
        if (have_next) {
            #pragma unroll
            for (int it = 0; it < 2; it++) {
                int r = a_r0 + it * 64;
                float vv[4] = {pref[it].x, pref[it].y, pref[it].z, pref[it].w};
                #pragma unroll
                for (int j = 0; j < 4; j++) {
                    float2* p = reinterpret_cast<float2*>(
                        nstc + ASD_OFF + ((a_kq + j) * 2 * BM + 2 * r) * 4);
                    *p = make_float2(vv[j], vv[j]);
                }
            }
            CP_ASYNC_WAIT0();
            __syncthreads();
        }
    }

    // ---- epilogue: bias (+relu), float4 stores ----
    #pragma unroll
    for (int i = 0; i < 8; i++) {
        int row = block_row + ty * 8 + i;
        if (row >= M) continue;
        #pragma unroll
        for (int jh = 0; jh < 2; jh++) {
            int col = block_col + tx * 8 + jh * 4;
            float2 p0 = *reinterpret_cast<float2*>(&acc[i][jh * 2]);
            float2 p1 = *reinterpret_cast<float2*>(&acc[i][jh * 2 + 1]);
            float4 v;
            v.x = p0.x + bias[col + 0];
            v.y = p0.y + bias[col + 1];
            v.z = p1.x + bias[col + 2];
            v.w = p1.y + bias[col + 3];
            if (relu) {
                v.x = fmaxf(v.x, 0.f); v.y = fmaxf(v.y, 0.f);
                v.z = fmaxf(v.z, 0.f); v.w = fmaxf(v.w, 0.f);
            }
            *reinterpret_cast<float4*>(Out + (size_t)row * D + col) = v;
        }
    }
}

// ============================================================================
// Edge scatter-add: dst[dstIdx[e]] += src[srcIdx[e]]  (rows of 256 floats)
// Vector reduction: one red.global.add.v4.f32 per float4 chunk (sm_90 base).
// ============================================================================
__global__ void scatter_add_kernel(
    const float4* __restrict__ src, const int* __restrict__ srcIdx,
    const int* __restrict__ dstIdx, float* __restrict__ dst, int E)
{
    long long idx = (long long)blockIdx.x * blockDim.x + threadIdx.x;
    if (idx >= (long long)E * 64) return;
    int e = (int)(idx >> 6);
    int c = (int)(idx & 63);
    float4 v = src[(size_t)srcIdx[e] * 64 + c];
    float* d = dst + ((size_t)dstIdx[e] * (size_t)D + (size_t)c * 4);
    asm volatile("red.global.add.v4.f32 [%0], {%1, %2, %3, %4};"
                 :: "l"(d), "f"(v.x), "f"(v.y), "f"(v.z), "f"(v.w) : "memory");
}

// ============================================================================
// Launcher
// ============================================================================
extern "C" void kernel_launch(void* const* d_in, const int* in_sizes, int n_in,
                              void* d_out, int out_size)
{
    int base = n_in - 24;
    if (base < 0) base = 0;

    const int*   ledge  = (const int*)  d_in[base + 0];
    const int*   cedge  = (const int*)  d_in[base + 1];
    const float* l_emb0 = (const float*)d_in[base + 2];
    const float* c_emb0 = (const float*)d_in[base + 3];

    const int E = in_sizes[base + 0];
    const int L = in_sizes[base + 2] / D;
    const int C = in_sizes[base + 3] / D;

    const float* mlp[5][4]; // [l2c, c2l, l2l, cu, lu] x [W1,b1,W2,b2]
    for (int m = 0; m < 5; m++)
        for (int p = 0; p < 4; p++)
            mlp[m][p] = (const float*)d_in[base + 4 + m * 4 + p];

    float *hid, *lfeat, *l2lbuf, *laggr, *cfeat, *caggr;
    cudaGetSymbolAddress((void**)&hid,    g_hid);
    cudaGetSymbolAddress((void**)&lfeat,  g_lfeat);
    cudaGetSymbolAddress((void**)&l2lbuf, g_l2l);
    cudaGetSymbolAddress((void**)&laggr,  g_laggr);
    cudaGetSymbolAddress((void**)&cfeat,  g_cfeat);
    cudaGetSymbolAddress((void**)&caggr,  g_caggr);

    cudaFuncSetAttribute(gemm_f32x2, cudaFuncAttributeMaxDynamicSharedMemorySize, SMEM_REQ);

    float* l_hist = (float*)d_out;
    float* c_hist = l_hist + (size_t)5 * L * D;
    const size_t LD = (size_t)L * D;
    const size_t CD = (size_t)C * D;

    cudaMemcpyAsync(l_hist, l_emb0, LD * sizeof(float), cudaMemcpyDeviceToDevice);
    cudaMemcpyAsync(c_hist, c_emb0, CD * sizeof(float), cudaMemcpyDeviceToDevice);

    const dim3 blk(256);
    const dim3 gridL(BN / 128 + 1, (L + BM - 1) / BM);   // (2, rows)
    const dim3 gridC(2, (C + BM - 1) / BM);
    const int sc_blocks = (int)(((long long)E * 64 + 255) / 256);

    for (int t = 0; t < 4; t++) {
        const float* lpre = l_hist + (size_t)t * LD;
        const float* cpre = c_hist + (size_t)t * CD;
        float* lnew = l_hist + (size_t)(t + 1) * LD;
        float* cnew = c_hist + (size_t)(t + 1) * CD;

        // l2c features: lfeat = MLP_l2c(lpre)
        gemm_f32x2<<<gridL, blk, SMEM_REQ>>>(lpre, 0, 0, mlp[0][0], mlp[0][1], hid,   L, 1, 0, 1);
        gemm_f32x2<<<gridL, blk, SMEM_REQ>>>(hid,  0, 0, mlp[0][2], mlp[0][3], lfeat, L, 1, 0, 0);
        // c2l features: cfeat = MLP_c2l(cpre)
        gemm_f32x2<<<gridC, blk, SMEM_REQ>>>(cpre, 0, 0, mlp[1][0], mlp[1][1], hid,   C, 1, 0, 1);
        gemm_f32x2<<<gridC, blk, SMEM_REQ>>>(hid,  0, 0, mlp[1][2], mlp[1][3], cfeat, C, 1, 0, 0);
        // l2l message (pair-swap on A)
        gemm_f32x2<<<gridL, blk, SMEM_REQ>>>(lpre, 0, 0, mlp[2][0], mlp[2][1], hid,    L, 1, 1, 1);
        gemm_f32x2<<<gridL, blk, SMEM_REQ>>>(hid,  0, 0, mlp[2][2], mlp[2][3], l2lbuf, L, 1, 0, 0);

        // clause aggregation
        cudaMemsetAsync(caggr, 0, CD * sizeof(float));
        scatter_add_kernel<<<sc_blocks, 256>>>((const float4*)lfeat, ledge, cedge, caggr, E);
        // clause update: [cpre, caggr] -> cnew
        gemm_f32x2<<<gridC, blk, SMEM_REQ>>>(cpre, caggr, 0, mlp[3][0], mlp[3][1], hid, C, 2, 0, 1);
        gemm_f32x2<<<gridC, blk, SMEM_REQ>>>(hid, 0, 0, mlp[3][2], mlp[3][3], cnew, C, 1, 0, 0);

        // literal aggregation
        cudaMemsetAsync(laggr, 0, LD * sizeof(float));
        scatter_add_kernel<<<sc_blocks, 256>>>((const float4*)cfeat, cedge, ledge, laggr, E);
        // literal update: [lpre, laggr, l2lbuf] -> lnew
        gemm_f32x2<<<gridL, blk, SMEM_REQ>>>(lpre, laggr, l2lbuf, mlp[4][0], mlp[4][1], hid, L, 3, 0, 1);
        gemm_f32x2<<<gridL, blk, SMEM_REQ>>>(hid, 0, 0, mlp[4][2], mlp[4][3], lnew, L, 1, 0, 0);
    }
}

// round 10
// speedup vs baseline: 2.3381x; 2.3381x over previous
#include <cuda_runtime.h>
#include <cuda_bf16.h>
#include <stdint.h>
#include <stddef.h>

#define D 256
#define LMAX 100000
#define CMAX 50000

// ---- scratch (device globals: allocation-free per harness rules) ----
__device__ float g_hid  [(size_t)LMAX * D];
__device__ float g_lfeat[(size_t)LMAX * D];
__device__ float g_l2l  [(size_t)LMAX * D];
__device__ float g_laggr[(size_t)LMAX * D];
__device__ float g_cfeat[(size_t)CMAX * D];
__device__ float g_caggr[(size_t)CMAX * D];

// ---- bf16 hi/lo split weights, layout preserved [Ktot][256] (n contiguous) ----
#define WT_TOTAL 851968
__device__ __nv_bfloat16 g_wt_hi[WT_TOTAL];
__device__ __nv_bfloat16 g_wt_lo[WT_TOTAL];

// ---- base-target PTX helpers (sm_80-era: legal under compute_103 base) ----
__device__ __forceinline__ uint32_t smem_u32(const void* p) {
    uint32_t a;
    asm("{ .reg .u64 t; cvta.to.shared.u64 t, %1; cvt.u32.u64 %0, t; }" : "=r"(a) : "l"(p));
    return a;
}
__device__ __forceinline__ void cp_async16(uint32_t dst, const void* src) {
    asm volatile("cp.async.cg.shared.global [%0], [%1], 16;" :: "r"(dst), "l"(src));
}
#define CP_ASYNC_COMMIT() asm volatile("cp.async.commit_group;" ::: "memory")
#define CP_ASYNC_WAIT0()  asm volatile("cp.async.wait_group 0;" ::: "memory")

#define LDSM4(R, addr)                                                          \
    asm volatile("ldmatrix.sync.aligned.m8n8.x4.shared.b16 {%0,%1,%2,%3}, [%4];" \
        : "=r"((R)[0]), "=r"((R)[1]), "=r"((R)[2]), "=r"((R)[3]) : "r"(addr))
#define LDSM4T(R, addr)                                                         \
    asm volatile("ldmatrix.sync.aligned.m8n8.x4.trans.shared.b16 {%0,%1,%2,%3}, [%4];" \
        : "=r"((R)[0]), "=r"((R)[1]), "=r"((R)[2]), "=r"((R)[3]) : "r"(addr))

#define MMA16816(C, A, B0, B1)                                                  \
    asm volatile("mma.sync.aligned.m16n8k16.row.col.f32.bf16.bf16.f32 "         \
        "{%0,%1,%2,%3}, {%4,%5,%6,%7}, {%8,%9}, {%0,%1,%2,%3};"                 \
        : "+f"((C)[0]), "+f"((C)[1]), "+f"((C)[2]), "+f"((C)[3])                \
        : "r"((A)[0]), "r"((A)[1]), "r"((A)[2]), "r"((A)[3]), "r"(B0), "r"(B1))

// ============================================================================
// Weight prep: fp32 -> bf16 hi/lo (elementwise, layout preserved)
// ============================================================================
__global__ void split_kernel(const float* __restrict__ W,
                             __nv_bfloat16* __restrict__ hi,
                             __nv_bfloat16* __restrict__ lo, int total) {
    int idx = blockIdx.x * blockDim.x + threadIdx.x;
    if (idx >= total) return;
    float x = W[idx];
    __nv_bfloat16 h = __float2bfloat16(x);
    hi[idx] = h;
    lo[idx] = __float2bfloat16(x - __bfloat162float(h));
}

// ============================================================================
// HMMA GEMM: Out[M,256] = act( sum_s A_s[M,256] @ W[s*256:(s+1)*256,:] + bias )
// 3-term bf16 split (Ah*Bh + Ah*Bl + Al*Bh), fp32 accum.
// CTA 128x128, 8 warps (32x64 each), BK=32, double-buffered SMEM.
// A rows padded to 80B (conflict-free ldmatrix); B XOR-swizzled 16B chunks.
// ============================================================================
#define BM 128
#define BN 128
#define TBK 32
#define A_STRIDE 80                 // 32 bf16 data + 8 pad = 80 bytes/row
#define AH_OFF 0                    // 128 * 80 = 10240
#define AL_OFF 10240
#define BH_OFF 20480                // 32 * 256 = 8192
#define BL_OFF 28672
#define STAGE  36864
#define SMEM_REQ (2 * STAGE)

__global__ __launch_bounds__(256, 1) void gemm_mma(
    const float* __restrict__ A0, const float* __restrict__ A1,
    const float* __restrict__ A2,
    const __nv_bfloat16* __restrict__ Wh, const __nv_bfloat16* __restrict__ Wl,
    const float* __restrict__ bias, float* __restrict__ Out,
    int M, int nseg, int swap0, int relu)
{
    extern __shared__ char sm[];
    const uint32_t smb = smem_u32(sm);
    const int tid  = threadIdx.x;
    const int lane = tid & 31;
    const int wid  = tid >> 5;
    const int wr   = wid & 3;               // warp m-row (32 rows each)
    const int wc   = wid >> 2;              // warp n-col (64 cols each)
    const int block_row = blockIdx.y * BM;
    const int block_col = blockIdx.x * BN;

    const float* Aseg[3] = {A0, A1, A2};
    const int T = nseg * 8;                 // 32-wide k-chunks

    float acc[2][8][4];
    #pragma unroll
    for (int i = 0; i < 2; i++)
        #pragma unroll
        for (int j = 0; j < 8; j++)
            #pragma unroll
            for (int q = 0; q < 4; q++) acc[i][j][q] = 0.f;

    const int a_r = tid & 127;              // A row handled by this thread
    const int a_h = tid >> 7;               // 0/1 -> k-chunk low half

    // B cp.async coords: idx = tid + it*256 -> k = idx>>4, chunk cn = idx&15
    // A ldmatrix-friendly STS chunks: chunk = q*2 + a_h (q=0,1)

    // ---------------- prologue: tile 0 -> stage 0 ----------------
    {
        // B
        #pragma unroll
        for (int term = 0; term < 2; term++) {
            const __nv_bfloat16* Wt = term ? Wl : Wh;
            uint32_t off = term ? BL_OFF : BH_OFF;
            #pragma unroll
            for (int it = 0; it < 2; it++) {
                int idx = tid + it * 256;
                int k = idx >> 4, cn = idx & 15;
                cp_async16(smb + off + (uint32_t)(k * 256 + ((cn ^ (k & 7)) << 4)),
                           Wt + (size_t)k * D + block_col + cn * 8);
            }
        }
        CP_ASYNC_COMMIT();
        // A: LDG fp32 -> split -> STS
        {
            const float* A = Aseg[0];
            int row = block_row + a_r;
            int ar = (swap0 && row < M) ? (row ^ 1) : row;
            float4 pa[4];
            if (row < M) {
                const float* ap = A + (size_t)ar * D + a_h * 8;
                pa[0] = *reinterpret_cast<const float4*>(ap);
                pa[1] = *reinterpret_cast<const float4*>(ap + 4);
                pa[2] = *reinterpret_cast<const float4*>(ap + 16);
                pa[3] = *reinterpret_cast<const float4*>(ap + 20);
            } else {
                pa[0] = pa[1] = pa[2] = pa[3] = make_float4(0.f, 0.f, 0.f, 0.f);
            }
            #pragma unroll
            for (int q = 0; q < 2; q++) {
                float f[8] = {pa[2*q].x, pa[2*q].y, pa[2*q].z, pa[2*q].w,
                              pa[2*q+1].x, pa[2*q+1].y, pa[2*q+1].z, pa[2*q+1].w};
                uint4 hv, lv;
                __nv_bfloat16* hp = reinterpret_cast<__nv_bfloat16*>(&hv);
                __nv_bfloat16* lp = reinterpret_cast<__nv_bfloat16*>(&lv);
                #pragma unroll
                for (int j = 0; j < 8; j++) {
                    __nv_bfloat16 h = __float2bfloat16(f[j]);
                    hp[j] = h;
                    lp[j] = __float2bfloat16(f[j] - __bfloat162float(h));
                }
                int chunk = q * 2 + a_h;
                *reinterpret_cast<uint4*>(sm + AH_OFF + a_r * A_STRIDE + chunk * 16) = hv;
                *reinterpret_cast<uint4*>(sm + AL_OFF + a_r * A_STRIDE + chunk * 16) = lv;
            }
        }
        CP_ASYNC_WAIT0();
        __syncthreads();
    }

    // ---------------- main loop ----------------
    for (int t = 0; t < T; t++) {
        const int cur = t & 1;
        const uint32_t sbase = smb + (uint32_t)cur * STAGE;
        char* nstc = sm + (size_t)(1 - cur) * STAGE;
        const uint32_t nsb = smb + (uint32_t)(1 - cur) * STAGE;
        const bool have_next = (t + 1 < T);

        float4 pa[4];
        if (have_next) {
            int tn = t + 1;
            // B for next tile
            #pragma unroll
            for (int term = 0; term < 2; term++) {
                const __nv_bfloat16* Wt = term ? Wl : Wh;
                uint32_t off = term ? BL_OFF : BH_OFF;
                const __nv_bfloat16* Wrow = Wt + (size_t)tn * TBK * D;
                #pragma unroll
                for (int it = 0; it < 2; it++) {
                    int idx = tid + it * 256;
                    int k = idx >> 4, cn = idx & 15;
                    cp_async16(nsb + off + (uint32_t)(k * 256 + ((cn ^ (k & 7)) << 4)),
                               Wrow + (size_t)k * D + block_col + cn * 8);
                }
            }
            CP_ASYNC_COMMIT();
            // A for next tile -> regs
            int s = tn >> 3, kloc = (tn & 7) * TBK;
            const float* A = Aseg[s];
            const bool swp = (s == 0) && swap0;
            int row = block_row + a_r;
            int ar = (swp && row < M) ? (row ^ 1) : row;
            if (row < M) {
                const float* ap = A + (size_t)ar * D + kloc + a_h * 8;
                pa[0] = *reinterpret_cast<const float4*>(ap);
                pa[1] = *reinterpret_cast<const float4*>(ap + 4);
                pa[2] = *reinterpret_cast<const float4*>(ap + 16);
                pa[3] = *reinterpret_cast<const float4*>(ap + 20);
            } else {
                pa[0] = pa[1] = pa[2] = pa[3] = make_float4(0.f, 0.f, 0.f, 0.f);
            }
        }

        // ---- compute current stage: two k16 sub-steps ----
        #pragma unroll
        for (int kk = 0; kk < TBK; kk += 16) {
            uint32_t ah[2][4], al[2][4];
            #pragma unroll
            for (int mt = 0; mt < 2; mt++) {
                uint32_t aaddr = sbase + AH_OFF
                    + (uint32_t)((wr * 32 + mt * 16 + (lane & 15)) * A_STRIDE)
                    + (uint32_t)(((kk >> 3) + (lane >> 4)) * 16);
                LDSM4(ah[mt], aaddr);
                LDSM4(al[mt], aaddr + (AL_OFF - AH_OFF));
            }
            uint32_t bh[4][4];
            #pragma unroll
            for (int nt = 0; nt < 4; nt++) {
                int n0 = wc * 64 + nt * 16;
                int k = kk + (lane & 15);
                int cn = (n0 >> 3) + (lane >> 4);
                uint32_t baddr = sbase + BH_OFF
                    + (uint32_t)(k * 256 + ((cn ^ (k & 7)) << 4));
                LDSM4T(bh[nt], baddr);
            }
            #pragma unroll
            for (int nt = 0; nt < 4; nt++)
                #pragma unroll
                for (int mt = 0; mt < 2; mt++) {
                    MMA16816(acc[mt][2*nt],   ah[mt], bh[nt][0], bh[nt][1]);
                    MMA16816(acc[mt][2*nt+1], ah[mt], bh[nt][2], bh[nt][3]);
                    MMA16816(acc[mt][2*nt],   al[mt], bh[nt][0], bh[nt][1]);
                    MMA16816(acc[mt][2*nt+1], al[mt], bh[nt][2], bh[nt][3]);
                }
            uint32_t bl[4][4];
            #pragma unroll
            for (int nt = 0; nt < 4; nt++) {
                int n0 = wc * 64 + nt * 16;
                int k = kk + (lane & 15);
                int cn = (n0 >> 3) + (lane >> 4);
                uint32_t baddr = sbase + BL_OFF
                    + (uint32_t)(k * 256 + ((cn ^ (k & 7)) << 4));
                LDSM4T(bl[nt], baddr);
            }
            #pragma unroll
            for (int nt = 0; nt < 4; nt++)
                #pragma unroll
                for (int mt = 0; mt < 2; mt++) {
                    MMA16816(acc[mt][2*nt],   ah[mt], bl[nt][0], bl[nt][1]);
                    MMA16816(acc[mt][2*nt+1], ah[mt], bl[nt][2], bl[nt][3]);
                }
        }

        if (have_next) {
            // publish next A tile
            #pragma unroll
            for (int q = 0; q < 2; q++) {
                float f[8] = {pa[2*q].x, pa[2*q].y, pa[2*q].z, pa[2*q].w,
                              pa[2*q+1].x, pa[2*q+1].y, pa[2*q+1].z, pa[2*q+1].w};
                uint4 hv, lv;
                __nv_bfloat16* hp = reinterpret_cast<__nv_bfloat16*>(&hv);
                __nv_bfloat16* lp = reinterpret_cast<__nv_bfloat16*>(&lv);
                #pragma unroll
                for (int j = 0; j < 8; j++) {
                    __nv_bfloat16 h = __float2bfloat16(f[j]);
                    hp[j] = h;
                    lp[j] = __float2bfloat16(f[j] - __bfloat162float(h));
                }
                int chunk = q * 2 + a_h;
                *reinterpret_cast<uint4*>(nstc + AH_OFF + a_r * A_STRIDE + chunk * 16) = hv;
                *reinterpret_cast<uint4*>(nstc + AL_OFF + a_r * A_STRIDE + chunk * 16) = lv;
            }
            CP_ASYNC_WAIT0();
            __syncthreads();
        }
    }

    // ---------------- epilogue: bias (+relu), float2 stores ----------------
    #pragma unroll
    for (int mt = 0; mt < 2; mt++) {
        #pragma unroll
        for (int nt = 0; nt < 8; nt++) {
            int row = block_row + wr * 32 + mt * 16 + (lane >> 2);
            int col = block_col + wc * 64 + nt * 8 + (lane & 3) * 2;
            float b0 = bias[col], b1 = bias[col + 1];
            float v0 = acc[mt][nt][0] + b0, v1 = acc[mt][nt][1] + b1;
            float v2 = acc[mt][nt][2] + b0, v3 = acc[mt][nt][3] + b1;
            if (relu) {
                v0 = fmaxf(v0, 0.f); v1 = fmaxf(v1, 0.f);
                v2 = fmaxf(v2, 0.f); v3 = fmaxf(v3, 0.f);
            }
            if (row < M)
                *reinterpret_cast<float2*>(Out + (size_t)row * D + col) = make_float2(v0, v1);
            if (row + 8 < M)
                *reinterpret_cast<float2*>(Out + (size_t)(row + 8) * D + col) = make_float2(v2, v3);
        }
    }
}

// ============================================================================
// Edge scatter-add: dst[dstIdx[e]] += src[srcIdx[e]]  (rows of 256 floats)
// ============================================================================
__global__ void scatter_add_kernel(
    const float4* __restrict__ src, const int* __restrict__ srcIdx,
    const int* __restrict__ dstIdx, float* __restrict__ dst, int E)
{
    long long idx = (long long)blockIdx.x * blockDim.x + threadIdx.x;
    if (idx >= (long long)E * 64) return;
    int e = (int)(idx >> 6);
    int c = (int)(idx & 63);
    float4 v = src[(size_t)srcIdx[e] * 64 + c];
    float* d = dst + ((size_t)dstIdx[e] * (size_t)D + (size_t)c * 4);
    asm volatile("red.global.add.v4.f32 [%0], {%1, %2, %3, %4};"
                 :: "l"(d), "f"(v.x), "f"(v.y), "f"(v.z), "f"(v.w) : "memory");
}

// ============================================================================
// Launcher
// ============================================================================
extern "C" void kernel_launch(void* const* d_in, const int* in_sizes, int n_in,
                              void* d_out, int out_size)
{
    int base = n_in - 24;
    if (base < 0) base = 0;

    const int*   ledge  = (const int*)  d_in[base + 0];
    const int*   cedge  = (const int*)  d_in[base + 1];
    const float* l_emb0 = (const float*)d_in[base + 2];
    const float* c_emb0 = (const float*)d_in[base + 3];

    const int E = in_sizes[base + 0];
    const int L = in_sizes[base + 2] / D;
    const int C = in_sizes[base + 3] / D;

    const float* mlp[5][4]; // [l2c, c2l, l2l, cu, lu] x [W1,b1,W2,b2]
    for (int m = 0; m < 5; m++)
        for (int p = 0; p < 4; p++)
            mlp[m][p] = (const float*)d_in[base + 4 + m * 4 + p];

    float *hid, *lfeat, *l2lbuf, *laggr, *cfeat, *caggr;
    cudaGetSymbolAddress((void**)&hid,    g_hid);
    cudaGetSymbolAddress((void**)&lfeat,  g_lfeat);
    cudaGetSymbolAddress((void**)&l2lbuf, g_l2l);
    cudaGetSymbolAddress((void**)&laggr,  g_laggr);
    cudaGetSymbolAddress((void**)&cfeat,  g_cfeat);
    cudaGetSymbolAddress((void**)&caggr,  g_caggr);
    __nv_bfloat16 *wth, *wtl;
    cudaGetSymbolAddress((void**)&wth, g_wt_hi);
    cudaGetSymbolAddress((void**)&wtl, g_wt_lo);

    cudaFuncSetAttribute(gemm_mma, cudaFuncAttributeMaxDynamicSharedMemorySize, SMEM_REQ);

    // ---- weight prep: bf16 hi/lo split, layout preserved [K][256] ----
    const size_t w1off[5] = {0, 65536, 131072, 196608, 327680};
    const int    w1K [5] = {256, 256, 256, 512, 768};
    const size_t w2off[5] = {524288, 589824, 655360, 720896, 786432};
    for (int m = 0; m < 5; m++) {
        int tot1 = w1K[m] * 256;
        split_kernel<<<(tot1 + 255) / 256, 256>>>(mlp[m][0], wth + w1off[m], wtl + w1off[m], tot1);
        split_kernel<<<(65536 + 255) / 256, 256>>>(mlp[m][2], wth + w2off[m], wtl + w2off[m], 65536);
    }

    float* l_hist = (float*)d_out;
    float* c_hist = l_hist + (size_t)5 * L * D;
    const size_t LD = (size_t)L * D;
    const size_t CD = (size_t)C * D;

    cudaMemcpyAsync(l_hist, l_emb0, LD * sizeof(float), cudaMemcpyDeviceToDevice);
    cudaMemcpyAsync(c_hist, c_emb0, CD * sizeof(float), cudaMemcpyDeviceToDevice);

    const dim3 blk(256);
    const dim3 gridL(2, (L + BM - 1) / BM);
    const dim3 gridC(2, (C + BM - 1) / BM);
    const int sc_blocks = (int)(((long long)E * 64 + 255) / 256);

    for (int t = 0; t < 4; t++) {
        const float* lpre = l_hist + (size_t)t * LD;
        const float* cpre = c_hist + (size_t)t * CD;
        float* lnew = l_hist + (size_t)(t + 1) * LD;
        float* cnew = c_hist + (size_t)(t + 1) * CD;

        // l2c features
        gemm_mma<<<gridL, blk, SMEM_REQ>>>(lpre, 0, 0, wth + w1off[0], wtl + w1off[0],
                                           mlp[0][1], hid,   L, 1, 0, 1);
        gemm_mma<<<gridL, blk, SMEM_REQ>>>(hid,  0, 0, wth + w2off[0], wtl + w2off[0],
                                           mlp[0][3], lfeat, L, 1, 0, 0);
        // c2l features
        gemm_mma<<<gridC, blk, SMEM_REQ>>>(cpre, 0, 0, wth + w1off[1], wtl + w1off[1],
                                           mlp[1][1], hid,   C, 1, 0, 1);
        gemm_mma<<<gridC, blk, SMEM_REQ>>>(hid,  0, 0, wth + w2off[1], wtl + w2off[1],
                                           mlp[1][3], cfeat, C, 1, 0, 0);
        // l2l message (pair-swap on A)
        gemm_mma<<<gridL, blk, SMEM_REQ>>>(lpre, 0, 0, wth + w1off[2], wtl + w1off[2],
                                           mlp[2][1], hid,    L, 1, 1, 1);
        gemm_mma<<<gridL, blk, SMEM_REQ>>>(hid,  0, 0, wth + w2off[2], wtl + w2off[2],
                                           mlp[2][3], l2lbuf, L, 1, 0, 0);

        // clause aggregation
        cudaMemsetAsync(caggr, 0, CD * sizeof(float));
        scatter_add_kernel<<<sc_blocks, 256>>>((const float4*)lfeat, ledge, cedge, caggr, E);
        // clause update: [cpre, caggr] -> cnew
        gemm_mma<<<gridC, blk, SMEM_REQ>>>(cpre, caggr, 0, wth + w1off[3], wtl + w1off[3],
                                           mlp[3][1], hid, C, 2, 0, 1);
        gemm_mma<<<gridC, blk, SMEM_REQ>>>(hid, 0, 0, wth + w2off[3], wtl + w2off[3],
                                           mlp[3][3], cnew, C, 1, 0, 0);

        // literal aggregation
        cudaMemsetAsync(laggr, 0, LD * sizeof(float));
        scatter_add_kernel<<<sc_blocks, 256>>>((const float4*)cfeat, cedge, ledge, laggr, E);
        // literal update: [lpre, laggr, l2lbuf] -> lnew
        gemm_mma<<<gridL, blk, SMEM_REQ>>>(lpre, laggr, l2lbuf, wth + w1off[4], wtl + w1off[4],
                                           mlp[4][1], hid, L, 3, 0, 1);
        gemm_mma<<<gridL, blk, SMEM_REQ>>>(hid, 0, 0, wth + w2off[4], wtl + w2off[4],
                                           mlp[4][3], lnew, L, 1, 0, 0);
    }
}

// round 12
// speedup vs baseline: 2.7032x; 1.1562x over previous
#include <cuda_runtime.h>
#include <cuda_bf16.h>
#include <stdint.h>
#include <stddef.h>

#define D 256
#define LMAX 100000
#define CMAX 50000

// ---- fp32 scratch (scatter sources/sinks only) ----
__device__ float g_lfeat[(size_t)LMAX * D];
__device__ float g_cfeat[(size_t)CMAX * D];
__device__ float g_laggr[(size_t)LMAX * D];
__device__ float g_caggr[(size_t)CMAX * D];

// ---- bf16 hi/lo activation pairs (GEMM A operands) ----
__device__ __nv_bfloat16 g_lpre_h[(size_t)LMAX * D], g_lpre_l[(size_t)LMAX * D];
__device__ __nv_bfloat16 g_cpre_h[(size_t)CMAX * D], g_cpre_l[(size_t)CMAX * D];
__device__ __nv_bfloat16 g_hid_h [(size_t)LMAX * D], g_hid_l [(size_t)LMAX * D];
__device__ __nv_bfloat16 g_l2l_h [(size_t)LMAX * D], g_l2l_l [(size_t)LMAX * D];
__device__ __nv_bfloat16 g_lag_h [(size_t)LMAX * D], g_lag_l [(size_t)LMAX * D];
__device__ __nv_bfloat16 g_cag_h [(size_t)CMAX * D], g_cag_l [(size_t)CMAX * D];

// ---- bf16 hi/lo split weights, layout preserved [Ktot][256] ----
#define WT_TOTAL 851968
__device__ __nv_bfloat16 g_wt_hi[WT_TOTAL];
__device__ __nv_bfloat16 g_wt_lo[WT_TOTAL];

// ---- base-target PTX helpers (sm_80-era; legal under compute_103 base) ----
__device__ __forceinline__ uint32_t smem_u32(const void* p) {
    uint32_t a;
    asm("{ .reg .u64 t; cvta.to.shared.u64 t, %1; cvt.u32.u64 %0, t; }" : "=r"(a) : "l"(p));
    return a;
}
__device__ __forceinline__ void cp_async16(uint32_t dst, const void* src) {
    asm volatile("cp.async.cg.shared.global [%0], [%1], 16;" :: "r"(dst), "l"(src));
}
#define CP_ASYNC_COMMIT() asm volatile("cp.async.commit_group;" ::: "memory")
#define CP_ASYNC_WAIT0()  asm volatile("cp.async.wait_group 0;" ::: "memory")

#define LDSM4(R, addr)                                                          \
    asm volatile("ldmatrix.sync.aligned.m8n8.x4.shared.b16 {%0,%1,%2,%3}, [%4];" \
        : "=r"((R)[0]), "=r"((R)[1]), "=r"((R)[2]), "=r"((R)[3]) : "r"(addr))
#define LDSM4T(R, addr)                                                         \
    asm volatile("ldmatrix.sync.aligned.m8n8.x4.trans.shared.b16 {%0,%1,%2,%3}, [%4];" \
        : "=r"((R)[0]), "=r"((R)[1]), "=r"((R)[2]), "=r"((R)[3]) : "r"(addr))

#define MMA16816(C, A, B0, B1)                                                  \
    asm volatile("mma.sync.aligned.m16n8k16.row.col.f32.bf16.bf16.f32 "         \
        "{%0,%1,%2,%3}, {%4,%5,%6,%7}, {%8,%9}, {%0,%1,%2,%3};"                 \
        : "+f"((C)[0]), "+f"((C)[1]), "+f"((C)[2]), "+f"((C)[3])                \
        : "r"((A)[0]), "r"((A)[1]), "r"((A)[2]), "r"((A)[3]), "r"(B0), "r"(B1))

// ============================================================================
// split: fp32 -> bf16 hi/lo (elementwise)
// ============================================================================
__global__ void split_kernel(const float* __restrict__ W,
                             __nv_bfloat16* __restrict__ hi,
                             __nv_bfloat16* __restrict__ lo, int total) {
    int idx = blockIdx.x * blockDim.x + threadIdx.x;
    if (idx >= total) return;
    float x = W[idx];
    __nv_bfloat16 h = __float2bfloat16(x);
    hi[idx] = h;
    lo[idx] = __float2bfloat16(x - __bfloat162float(h));
}

// ============================================================================
// HMMA GEMM, 3-term bf16 split, A pre-split bf16 (cp.async both operands).
// CTA 128x128, 8 warps (32x64), BK=32, double-buffered, 2 CTAs/SM target.
// Epilogue writes optional fp32 and/or bf16 hi/lo outputs.
// ============================================================================
#define BM 128
#define BN 128
#define TBK 32
#define A_STRIDE 80                 // 64B data + 16B pad -> conflict-free ldmatrix
#define AH_OFF 0                    // 128 * 80 = 10240
#define AL_OFF 10240
#define BH_OFF 20480                // 32 k x 128 n x 2B = 8192
#define BL_OFF 28672
#define STAGE  36864
#define SMEM_REQ (2 * STAGE)

__global__ __launch_bounds__(256, 2) void gemm_mma(
    const __nv_bfloat16* __restrict__ A0h, const __nv_bfloat16* __restrict__ A0l,
    const __nv_bfloat16* __restrict__ A1h, const __nv_bfloat16* __restrict__ A1l,
    const __nv_bfloat16* __restrict__ A2h, const __nv_bfloat16* __restrict__ A2l,
    const __nv_bfloat16* __restrict__ Wh, const __nv_bfloat16* __restrict__ Wl,
    const float* __restrict__ bias,
    float* __restrict__ OutF, __nv_bfloat16* __restrict__ OutH,
    __nv_bfloat16* __restrict__ OutL,
    int M, int nseg, int swap0, int relu)
{
    extern __shared__ char sm[];
    const uint32_t smb = smem_u32(sm);
    const int tid  = threadIdx.x;
    const int lane = tid & 31;
    const int wid  = tid >> 5;
    const int wr   = wid & 3;
    const int wc   = wid >> 2;
    const int block_row = blockIdx.y * BM;
    const int block_col = blockIdx.x * BN;

    const __nv_bfloat16* Ah[3] = {A0h, A1h, A2h};
    const __nv_bfloat16* Al[3] = {A0l, A1l, A2l};
    const int T = nseg * 8;

    float acc[2][8][4];
    #pragma unroll
    for (int i = 0; i < 2; i++)
        #pragma unroll
        for (int j = 0; j < 8; j++)
            #pragma unroll
            for (int q = 0; q < 4; q++) acc[i][j][q] = 0.f;

    // A cp.async coords: idx = tid + it*256 -> r = idx>>2 (0..127), cn = idx&3
    const int a_r  = tid >> 2;
    const int a_cn = tid & 3;

    // issue one stage's loads
    auto issue_stage = [&](int tn, uint32_t sb) {
        int s = tn >> 3, kloc = (tn & 7) * TBK;
        const bool swp = (s == 0) && swap0;
        // A hi/lo
        {
            int row0 = block_row + a_r;
            int ar0 = swp ? (row0 ^ 1) : row0;
            int row1 = block_row + a_r + 64;
            int ar1 = swp ? (row1 ^ 1) : row1;
            size_t s0 = (size_t)ar0 * D + kloc + a_cn * 8;
            size_t s1 = (size_t)ar1 * D + kloc + a_cn * 8;
            uint32_t d0 = sb + (uint32_t)(a_r * A_STRIDE + a_cn * 16);
            uint32_t d1 = sb + (uint32_t)((a_r + 64) * A_STRIDE + a_cn * 16);
            cp_async16(d0 + AH_OFF, Ah[s] + s0);
            cp_async16(d1 + AH_OFF, Ah[s] + s1);
            cp_async16(d0 + AL_OFF, Al[s] + s0);
            cp_async16(d1 + AL_OFF, Al[s] + s1);
        }
        // B hi/lo
        const __nv_bfloat16* WhR = Wh + (size_t)(s * D + (tn & 7) * TBK) * D;
        const __nv_bfloat16* WlR = Wl + (size_t)(s * D + (tn & 7) * TBK) * D;
        #pragma unroll
        for (int it = 0; it < 2; it++) {
            int idx = tid + it * 256;
            int k = idx >> 4, cn = idx & 15;
            uint32_t doff = (uint32_t)(k * 256 + ((cn ^ (k & 7)) << 4));
            size_t soff = (size_t)k * D + block_col + cn * 8;
            cp_async16(sb + BH_OFF + doff, WhR + soff);
            cp_async16(sb + BL_OFF + doff, WlR + soff);
        }
        CP_ASYNC_COMMIT();
    };

    // ---- prologue ----
    issue_stage(0, smb);
    CP_ASYNC_WAIT0();
    __syncthreads();

    // ---- main loop ----
    for (int t = 0; t < T; t++) {
        const uint32_t sbase = smb + (uint32_t)(t & 1) * STAGE;
        const bool have_next = (t + 1 < T);
        if (have_next)
            issue_stage(t + 1, smb + (uint32_t)((t + 1) & 1) * STAGE);

        #pragma unroll
        for (int kk = 0; kk < TBK; kk += 16) {
            uint32_t ah[2][4], al[2][4];
            #pragma unroll
            for (int mt = 0; mt < 2; mt++) {
                uint32_t aaddr = sbase + AH_OFF
                    + (uint32_t)((wr * 32 + mt * 16 + (lane & 15)) * A_STRIDE)
                    + (uint32_t)(((kk >> 3) + (lane >> 4)) * 16);
                LDSM4(ah[mt], aaddr);
                LDSM4(al[mt], aaddr + (AL_OFF - AH_OFF));
            }
            uint32_t bh[4][4];
            #pragma unroll
            for (int nt = 0; nt < 4; nt++) {
                int n0 = wc * 64 + nt * 16;
                int k = kk + (lane & 15);
                int cn = (n0 >> 3) + (lane >> 4);
                LDSM4T(bh[nt], sbase + BH_OFF
                    + (uint32_t)(k * 256 + ((cn ^ (k & 7)) << 4)));
            }
            #pragma unroll
            for (int nt = 0; nt < 4; nt++)
                #pragma unroll
                for (int mt = 0; mt < 2; mt++) {
                    MMA16816(acc[mt][2*nt],   ah[mt], bh[nt][0], bh[nt][1]);
                    MMA16816(acc[mt][2*nt+1], ah[mt], bh[nt][2], bh[nt][3]);
                    MMA16816(acc[mt][2*nt],   al[mt], bh[nt][0], bh[nt][1]);
                    MMA16816(acc[mt][2*nt+1], al[mt], bh[nt][2], bh[nt][3]);
                }
            uint32_t bl[4][4];
            #pragma unroll
            for (int nt = 0; nt < 4; nt++) {
                int n0 = wc * 64 + nt * 16;
                int k = kk + (lane & 15);
                int cn = (n0 >> 3) + (lane >> 4);
                LDSM4T(bl[nt], sbase + BL_OFF
                    + (uint32_t)(k * 256 + ((cn ^ (k & 7)) << 4)));
            }
            #pragma unroll
            for (int nt = 0; nt < 4; nt++)
                #pragma unroll
                for (int mt = 0; mt < 2; mt++) {
                    MMA16816(acc[mt][2*nt],   ah[mt], bl[nt][0], bl[nt][1]);
                    MMA16816(acc[mt][2*nt+1], ah[mt], bl[nt][2], bl[nt][3]);
                }
        }

        if (have_next) {
            CP_ASYNC_WAIT0();
            __syncthreads();
        }
    }

    // ---- epilogue ----
    #pragma unroll
    for (int mt = 0; mt < 2; mt++) {
        #pragma unroll
        for (int nt = 0; nt < 8; nt++) {
            int row = block_row + wr * 32 + mt * 16 + (lane >> 2);
            int col = block_col + wc * 64 + nt * 8 + (lane & 3) * 2;
            float b0 = bias[col], b1 = bias[col + 1];
            float v0 = acc[mt][nt][0] + b0, v1 = acc[mt][nt][1] + b1;
            float v2 = acc[mt][nt][2] + b0, v3 = acc[mt][nt][3] + b1;
            if (relu) {
                v0 = fmaxf(v0, 0.f); v1 = fmaxf(v1, 0.f);
                v2 = fmaxf(v2, 0.f); v3 = fmaxf(v3, 0.f);
            }
            if (OutF) {
                if (row < M)
                    *reinterpret_cast<float2*>(OutF + (size_t)row * D + col) = make_float2(v0, v1);
                if (row + 8 < M)
                    *reinterpret_cast<float2*>(OutF + (size_t)(row + 8) * D + col) = make_float2(v2, v3);
            }
            if (OutH) {
                __nv_bfloat16 h0 = __float2bfloat16(v0), h1 = __float2bfloat16(v1);
                __nv_bfloat16 h2 = __float2bfloat16(v2), h3 = __float2bfloat16(v3);
                __nv_bfloat162 hp0 = {h0, h1}, hp1 = {h2, h3};
                __nv_bfloat162 lp0 = {__float2bfloat16(v0 - __bfloat162float(h0)),
                                      __float2bfloat16(v1 - __bfloat162float(h1))};
                __nv_bfloat162 lp1 = {__float2bfloat16(v2 - __bfloat162float(h2)),
                                      __float2bfloat16(v3 - __bfloat162float(h3))};
                if (row < M) {
                    *reinterpret_cast<__nv_bfloat162*>(OutH + (size_t)row * D + col) = hp0;
                    *reinterpret_cast<__nv_bfloat162*>(OutL + (size_t)row * D + col) = lp0;
                }
                if (row + 8 < M) {
                    *reinterpret_cast<__nv_bfloat162*>(OutH + (size_t)(row + 8) * D + col) = hp1;
                    *reinterpret_cast<__nv_bfloat162*>(OutL + (size_t)(row + 8) * D + col) = lp1;
                }
            }
        }
    }
}

// ============================================================================
// Edge scatter-add: dst[dstIdx[e]] += src[srcIdx[e]]  (rows of 256 floats)
// ============================================================================
__global__ void scatter_add_kernel(
    const float4* __restrict__ src, const int* __restrict__ srcIdx,
    const int* __restrict__ dstIdx, float* __restrict__ dst, int E)
{
    long long idx = (long long)blockIdx.x * blockDim.x + threadIdx.x;
    if (idx >= (long long)E * 64) return;
    int e = (int)(idx >> 6);
    int c = (int)(idx & 63);
    float4 v = src[(size_t)srcIdx[e] * 64 + c];
    float* d = dst + ((size_t)dstIdx[e] * (size_t)D + (size_t)c * 4);
    asm volatile("red.global.add.v4.f32 [%0], {%1, %2, %3, %4};"
                 :: "l"(d), "f"(v.x), "f"(v.y), "f"(v.z), "f"(v.w) : "memory");
}

// ============================================================================
// Launcher
// ============================================================================
extern "C" void kernel_launch(void* const* d_in, const int* in_sizes, int n_in,
                              void* d_out, int out_size)
{
    int base = n_in - 24;
    if (base < 0) base = 0;

    const int*   ledge  = (const int*)  d_in[base + 0];
    const int*   cedge  = (const int*)  d_in[base + 1];
    const float* l_emb0 = (const float*)d_in[base + 2];
    const float* c_emb0 = (const float*)d_in[base + 3];

    const int E = in_sizes[base + 0];
    const int L = in_sizes[base + 2] / D;
    const int C = in_sizes[base + 3] / D;

    const float* mlp[5][4];
    for (int m = 0; m < 5; m++)
        for (int p = 0; p < 4; p++)
            mlp[m][p] = (const float*)d_in[base + 4 + m * 4 + p];

    float *lfeat, *cfeat, *laggr, *caggr;
    cudaGetSymbolAddress((void**)&lfeat, g_lfeat);
    cudaGetSymbolAddress((void**)&cfeat, g_cfeat);
    cudaGetSymbolAddress((void**)&laggr, g_laggr);
    cudaGetSymbolAddress((void**)&caggr, g_caggr);
    __nv_bfloat16 *lpre_h, *lpre_l, *cpre_h, *cpre_l, *hid_h, *hid_l;
    __nv_bfloat16 *l2l_h, *l2l_l, *lag_h, *lag_l, *cag_h, *cag_l, *wth, *wtl;
    cudaGetSymbolAddress((void**)&lpre_h, g_lpre_h);
    cudaGetSymbolAddress((void**)&lpre_l, g_lpre_l);
    cudaGetSymbolAddress((void**)&cpre_h, g_cpre_h);
    cudaGetSymbolAddress((void**)&cpre_l, g_cpre_l);
    cudaGetSymbolAddress((void**)&hid_h,  g_hid_h);
    cudaGetSymbolAddress((void**)&hid_l,  g_hid_l);
    cudaGetSymbolAddress((void**)&l2l_h,  g_l2l_h);
    cudaGetSymbolAddress((void**)&l2l_l,  g_l2l_l);
    cudaGetSymbolAddress((void**)&lag_h,  g_lag_h);
    cudaGetSymbolAddress((void**)&lag_l,  g_lag_l);
    cudaGetSymbolAddress((void**)&cag_h,  g_cag_h);
    cudaGetSymbolAddress((void**)&cag_l,  g_cag_l);
    cudaGetSymbolAddress((void**)&wth, g_wt_hi);
    cudaGetSymbolAddress((void**)&wtl, g_wt_lo);

    cudaFuncSetAttribute(gemm_mma, cudaFuncAttributeMaxDynamicSharedMemorySize, SMEM_REQ);

    // ---- weight prep ----
    const size_t w1off[5] = {0, 65536, 131072, 196608, 327680};
    const int    w1K [5] = {256, 256, 256, 512, 768};
    const size_t w2off[5] = {524288, 589824, 655360, 720896, 786432};
    for (int m = 0; m < 5; m++) {
        int tot1 = w1K[m] * 256;
        split_kernel<<<(tot1 + 255) / 256, 256>>>(mlp[m][0], wth + w1off[m], wtl + w1off[m], tot1);
        split_kernel<<<(65536 + 255) / 256, 256>>>(mlp[m][2], wth + w2off[m], wtl + w2off[m], 65536);
    }

    float* l_hist = (float*)d_out;
    float* c_hist = l_hist + (size_t)5 * L * D;
    const size_t LD = (size_t)L * D;
    const size_t CD = (size_t)C * D;

    cudaMemcpyAsync(l_hist, l_emb0, LD * sizeof(float), cudaMemcpyDeviceToDevice);
    cudaMemcpyAsync(c_hist, c_emb0, CD * sizeof(float), cudaMemcpyDeviceToDevice);
    // initial activation splits
    split_kernel<<<(int)((LD + 255) / 256), 256>>>(l_emb0, lpre_h, lpre_l, (int)LD);
    split_kernel<<<(int)((CD + 255) / 256), 256>>>(c_emb0, cpre_h, cpre_l, (int)CD);

    const dim3 blk(256);
    const dim3 gridL(2, (L + BM - 1) / BM);
    const dim3 gridC(2, (C + BM - 1) / BM);
    const int sc_blocks = (int)(((long long)E * 64 + 255) / 256);
    const __nv_bfloat16* Z = nullptr;
    float* ZF = nullptr;
    __nv_bfloat16* ZB = nullptr;

    for (int t = 0; t < 4; t++) {
        float* lnew = l_hist + (size_t)(t + 1) * LD;
        float* cnew = c_hist + (size_t)(t + 1) * CD;

        // l2c features: hid(bf16) -> lfeat(fp32)
        gemm_mma<<<gridL, blk, SMEM_REQ>>>(lpre_h, lpre_l, Z, Z, Z, Z,
            wth + w1off[0], wtl + w1off[0], mlp[0][1], ZF, hid_h, hid_l, L, 1, 0, 1);
        gemm_mma<<<gridL, blk, SMEM_REQ>>>(hid_h, hid_l, Z, Z, Z, Z,
            wth + w2off[0], wtl + w2off[0], mlp[0][3], lfeat, ZB, ZB, L, 1, 0, 0);
        // c2l features
        gemm_mma<<<gridC, blk, SMEM_REQ>>>(cpre_h, cpre_l, Z, Z, Z, Z,
            wth + w1off[1], wtl + w1off[1], mlp[1][1], ZF, hid_h, hid_l, C, 1, 0, 1);
        gemm_mma<<<gridC, blk, SMEM_REQ>>>(hid_h, hid_l, Z, Z, Z, Z,
            wth + w2off[1], wtl + w2off[1], mlp[1][3], cfeat, ZB, ZB, C, 1, 0, 0);
        // l2l message (pair-swap on A), bf16-only output
        gemm_mma<<<gridL, blk, SMEM_REQ>>>(lpre_h, lpre_l, Z, Z, Z, Z,
            wth + w1off[2], wtl + w1off[2], mlp[2][1], ZF, hid_h, hid_l, L, 1, 1, 1);
        gemm_mma<<<gridL, blk, SMEM_REQ>>>(hid_h, hid_l, Z, Z, Z, Z,
            wth + w2off[2], wtl + w2off[2], mlp[2][3], ZF, l2l_h, l2l_l, L, 1, 0, 0);

        // clause aggregation + split
        cudaMemsetAsync(caggr, 0, CD * sizeof(float));
        scatter_add_kernel<<<sc_blocks, 256>>>((const float4*)lfeat, ledge, cedge, caggr, E);
        split_kernel<<<(int)((CD + 255) / 256), 256>>>(caggr, cag_h, cag_l, (int)CD);
        // clause update: [cpre, caggr] -> cnew (fp32 hist + cpre bf16 pair)
        gemm_mma<<<gridC, blk, SMEM_REQ>>>(cpre_h, cpre_l, cag_h, cag_l, Z, Z,
            wth + w1off[3], wtl + w1off[3], mlp[3][1], ZF, hid_h, hid_l, C, 2, 0, 1);
        gemm_mma<<<gridC, blk, SMEM_REQ>>>(hid_h, hid_l, Z, Z, Z, Z,
            wth + w2off[3], wtl + w2off[3], mlp[3][3], cnew, cpre_h, cpre_l, C, 1, 0, 0);

        // literal aggregation + split
        cudaMemsetAsync(laggr, 0, LD * sizeof(float));
        scatter_add_kernel<<<sc_blocks, 256>>>((const float4*)cfeat, cedge, ledge, laggr, E);
        split_kernel<<<(int)((LD + 255) / 256), 256>>>(laggr, lag_h, lag_l, (int)LD);
        // literal update: [lpre, laggr, l2l] -> lnew (fp32 hist + lpre bf16 pair)
        gemm_mma<<<gridL, blk, SMEM_REQ>>>(lpre_h, lpre_l, lag_h, lag_l, l2l_h, l2l_l,
            wth + w1off[4], wtl + w1off[4], mlp[4][1], ZF, hid_h, hid_l, L, 3, 0, 1);
        gemm_mma<<<gridL, blk, SMEM_REQ>>>(hid_h, hid_l, Z, Z, Z, Z,
            wth + w2off[4], wtl + w2off[4], mlp[4][3], lnew, lpre_h, lpre_l, L, 1, 0, 0);
    }
}

// round 13
// speedup vs baseline: 2.7148x; 1.0043x over previous
#include <cuda_runtime.h>
#include <cuda_bf16.h>
#include <stdint.h>
#include <stddef.h>

#define D 256
#define LMAX 100000
#define CMAX 50000

// ---- fp32 scratch (scatter sources/sinks only) ----
__device__ float g_lfeat[(size_t)LMAX * D];
__device__ float g_cfeat[(size_t)CMAX * D];
__device__ float g_laggr[(size_t)LMAX * D];
__device__ float g_caggr[(size_t)CMAX * D];

// ---- bf16 hi/lo activation pairs (GEMM A operands) ----
__device__ __nv_bfloat16 g_lpre_h[(size_t)LMAX * D], g_lpre_l[(size_t)LMAX * D];
__device__ __nv_bfloat16 g_cpre_h[(size_t)CMAX * D], g_cpre_l[(size_t)CMAX * D];
__device__ __nv_bfloat16 g_l2l_h [(size_t)LMAX * D], g_l2l_l [(size_t)LMAX * D];
__device__ __nv_bfloat16 g_lag_h [(size_t)LMAX * D], g_lag_l [(size_t)LMAX * D];
__device__ __nv_bfloat16 g_cag_h [(size_t)CMAX * D], g_cag_l [(size_t)CMAX * D];

// ---- bf16 hi/lo split weights, layout preserved [Ktot][256] ----
#define WT_TOTAL 851968
__device__ __nv_bfloat16 g_wt_hi[WT_TOTAL];
__device__ __nv_bfloat16 g_wt_lo[WT_TOTAL];

// ---- base-target PTX helpers ----
__device__ __forceinline__ uint32_t smem_u32(const void* p) {
    uint32_t a;
    asm("{ .reg .u64 t; cvta.to.shared.u64 t, %1; cvt.u32.u64 %0, t; }" : "=r"(a) : "l"(p));
    return a;
}
__device__ __forceinline__ void cp_async16(uint32_t dst, const void* src) {
    asm volatile("cp.async.cg.shared.global [%0], [%1], 16;" :: "r"(dst), "l"(src));
}
#define CP_ASYNC_COMMIT() asm volatile("cp.async.commit_group;" ::: "memory")
#define CP_ASYNC_WAIT0()  asm volatile("cp.async.wait_group 0;" ::: "memory")

#define LDSM4(R, addr)                                                          \
    asm volatile("ldmatrix.sync.aligned.m8n8.x4.shared.b16 {%0,%1,%2,%3}, [%4];" \
        : "=r"((R)[0]), "=r"((R)[1]), "=r"((R)[2]), "=r"((R)[3]) : "r"(addr))
#define LDSM4T(R, addr)                                                         \
    asm volatile("ldmatrix.sync.aligned.m8n8.x4.trans.shared.b16 {%0,%1,%2,%3}, [%4];" \
        : "=r"((R)[0]), "=r"((R)[1]), "=r"((R)[2]), "=r"((R)[3]) : "r"(addr))

#define MMA16816(C, A, B0, B1)                                                  \
    asm volatile("mma.sync.aligned.m16n8k16.row.col.f32.bf16.bf16.f32 "         \
        "{%0,%1,%2,%3}, {%4,%5,%6,%7}, {%8,%9}, {%0,%1,%2,%3};"                 \
        : "+f"((C)[0]), "+f"((C)[1]), "+f"((C)[2]), "+f"((C)[3])                \
        : "r"((A)[0]), "r"((A)[1]), "r"((A)[2]), "r"((A)[3]), "r"(B0), "r"(B1))

// ============================================================================
// split: fp32 -> bf16 hi/lo
// ============================================================================
__global__ void split_kernel(const float* __restrict__ W,
                             __nv_bfloat16* __restrict__ hi,
                             __nv_bfloat16* __restrict__ lo, int total) {
    int idx = blockIdx.x * blockDim.x + threadIdx.x;
    if (idx >= total) return;
    float x = W[idx];
    __nv_bfloat16 h = __float2bfloat16(x);
    hi[idx] = h;
    lo[idx] = __float2bfloat16(x - __bfloat162float(h));
}

// ============================================================================
// Fused 2-layer MLP: Out = (relu(sum_s A_s @ W1_s + b1)) @ W2 + b2
// 3-term bf16 split HMMA. CTA = 128 rows x full 256 cols; 512 threads,
// 16 warps (4x4), warp tile 32x64, BK=32 double-buffered; hidden in SMEM.
// ============================================================================
#define BM 128
#define TBK 32
#define B_ST(st)   (2048 + (st) * 32768)
#define B_LO       16384
#define A_ST(st)   (67584 + (st) * 20480)
#define A_LO       10240
#define A_STRIDE   80
#define HID_HI     67584
#define HID_LO     135168
#define HID_STRIDE 528
#define SMEM_REQ   202752

__global__ __launch_bounds__(512, 1) void mlp_fused(
    const __nv_bfloat16* __restrict__ A0h, const __nv_bfloat16* __restrict__ A0l,
    const __nv_bfloat16* __restrict__ A1h, const __nv_bfloat16* __restrict__ A1l,
    const __nv_bfloat16* __restrict__ A2h, const __nv_bfloat16* __restrict__ A2l,
    const __nv_bfloat16* __restrict__ W1h, const __nv_bfloat16* __restrict__ W1l,
    const __nv_bfloat16* __restrict__ W2h, const __nv_bfloat16* __restrict__ W2l,
    const float* __restrict__ b1, const float* __restrict__ b2,
    float* __restrict__ OutF, __nv_bfloat16* __restrict__ OutH,
    __nv_bfloat16* __restrict__ OutL,
    int M, int nseg, int swap0)
{
    extern __shared__ char sm[];
    const uint32_t smb = smem_u32(sm);
    const int tid  = threadIdx.x;
    const int lane = tid & 31;
    const int wid  = tid >> 5;
    const int wr   = wid & 3;
    const int wc   = wid >> 2;
    const int block_row = blockIdx.x * BM;

    const __nv_bfloat16* Ah[3] = {A0h, A1h, A2h};
    const __nv_bfloat16* Al[3] = {A0l, A1l, A2l};

    if (tid < 256) {
        reinterpret_cast<float*>(sm)[tid] = b1[tid];
        reinterpret_cast<float*>(sm + 1024)[tid] = b2[tid];
    }

    float acc[2][8][4];
    #pragma unroll
    for (int i = 0; i < 2; i++)
        #pragma unroll
        for (int j = 0; j < 8; j++)
            #pragma unroll
            for (int q = 0; q < 4; q++) acc[i][j][q] = 0.f;

    auto issue_B = [&](const __nv_bfloat16* Wh_, const __nv_bfloat16* Wl_, uint32_t sb) {
        #pragma unroll
        for (int it = 0; it < 2; it++) {
            int idx = tid + it * 512;
            int k = idx >> 5, cn = idx & 31;
            uint32_t doff = (uint32_t)(k * 512 + ((cn ^ (k & 7)) << 4));
            size_t soff = (size_t)k * D + cn * 8;
            cp_async16(sb + doff, Wh_ + soff);
            cp_async16(sb + B_LO + doff, Wl_ + soff);
        }
    };
    auto issue_A = [&](int s, int kloc, uint32_t sb) {
        const bool swp = (s == 0) && swap0;
        int row = block_row + (tid >> 2);
        int ar = swp ? (row ^ 1) : row;
        if (ar >= M) ar = M - 1;
        size_t soff = (size_t)ar * D + kloc + (tid & 3) * 8;
        uint32_t doff = (uint32_t)((tid >> 2) * A_STRIDE + (tid & 3) * 16);
        cp_async16(sb + doff, Ah[s] + soff);
        cp_async16(sb + A_LO + doff, Al[s] + soff);
    };

    // one k16 step; A hi at abase, A lo at abase+alo_delta
    auto mma_k16 = [&](uint32_t abase, int astride, uint32_t alo_delta,
                       uint32_t bbase, int kk) {
        uint32_t ah[2][4], al[2][4];
        #pragma unroll
        for (int mt = 0; mt < 2; mt++) {
            uint32_t aaddr = abase
                + (uint32_t)((wr * 32 + mt * 16 + (lane & 15)) * astride)
                + (uint32_t)(((kk >> 3) + (lane >> 4)) * 16);
            LDSM4(ah[mt], aaddr);
            LDSM4(al[mt], aaddr + alo_delta);
        }
        int kr = (kk & 31) + (lane & 15);
        uint32_t bh[4][4];
        #pragma unroll
        for (int nt = 0; nt < 4; nt++) {
            int cn = ((wc * 64 + nt * 16) >> 3) + (lane >> 4);
            LDSM4T(bh[nt], bbase + (uint32_t)(kr * 512 + ((cn ^ (kr & 7)) << 4)));
        }
        #pragma unroll
        for (int nt = 0; nt < 4; nt++)
            #pragma unroll
            for (int mt = 0; mt < 2; mt++) {
                MMA16816(acc[mt][2*nt],   ah[mt], bh[nt][0], bh[nt][1]);
                MMA16816(acc[mt][2*nt+1], ah[mt], bh[nt][2], bh[nt][3]);
                MMA16816(acc[mt][2*nt],   al[mt], bh[nt][0], bh[nt][1]);
                MMA16816(acc[mt][2*nt+1], al[mt], bh[nt][2], bh[nt][3]);
            }
        uint32_t bl[4][4];
        #pragma unroll
        for (int nt = 0; nt < 4; nt++) {
            int cn = ((wc * 64 + nt * 16) >> 3) + (lane >> 4);
            LDSM4T(bl[nt], bbase + B_LO + (uint32_t)(kr * 512 + ((cn ^ (kr & 7)) << 4)));
        }
        #pragma unroll
        for (int nt = 0; nt < 4; nt++)
            #pragma unroll
            for (int mt = 0; mt < 2; mt++) {
                MMA16816(acc[mt][2*nt],   ah[mt], bl[nt][0], bl[nt][1]);
                MMA16816(acc[mt][2*nt+1], ah[mt], bl[nt][2], bl[nt][3]);
            }
    };

    // ===== phase 1: L1 =====
    const int T1 = nseg * 8;
    issue_A(0, 0, smb + A_ST(0));
    issue_B(W1h, W1l, smb + B_ST(0));
    CP_ASYNC_COMMIT();
    CP_ASYNC_WAIT0();
    __syncthreads();

    for (int t = 0; t < T1; t++) {
        const int cur = t & 1;
        const bool have_next = (t + 1 < T1);
        if (have_next) {
            int tn = t + 1, s = tn >> 3, kloc = (tn & 7) * TBK;
            issue_A(s, kloc, smb + A_ST(tn & 1));
            issue_B(W1h + (size_t)(s * D + kloc) * D, W1l + (size_t)(s * D + kloc) * D,
                    smb + B_ST(tn & 1));
            CP_ASYNC_COMMIT();
        }
        mma_k16(smb + A_ST(cur), A_STRIDE, A_LO, smb + B_ST(cur), 0);
        mma_k16(smb + A_ST(cur), A_STRIDE, A_LO, smb + B_ST(cur), 16);
        if (have_next) { CP_ASYNC_WAIT0(); __syncthreads(); }
    }
    __syncthreads();

    // ===== phase 2: bias + relu + split -> SMEM hidden =====
    {
        const float* b1s = reinterpret_cast<const float*>(sm);
        #pragma unroll
        for (int mt = 0; mt < 2; mt++) {
            #pragma unroll
            for (int nt = 0; nt < 8; nt++) {
                int row = wr * 32 + mt * 16 + (lane >> 2);
                int col = wc * 64 + nt * 8 + (lane & 3) * 2;
                float bb0 = b1s[col], bb1 = b1s[col + 1];
                float v0 = fmaxf(acc[mt][nt][0] + bb0, 0.f);
                float v1 = fmaxf(acc[mt][nt][1] + bb1, 0.f);
                float v2 = fmaxf(acc[mt][nt][2] + bb0, 0.f);
                float v3 = fmaxf(acc[mt][nt][3] + bb1, 0.f);
                __nv_bfloat16 h0 = __float2bfloat16(v0), h1 = __float2bfloat16(v1);
                __nv_bfloat16 h2 = __float2bfloat16(v2), h3 = __float2bfloat16(v3);
                __nv_bfloat162 hp0 = {h0, h1}, hp1 = {h2, h3};
                __nv_bfloat162 lp0 = {__float2bfloat16(v0 - __bfloat162float(h0)),
                                      __float2bfloat16(v1 - __bfloat162float(h1))};
                __nv_bfloat162 lp1 = {__float2bfloat16(v2 - __bfloat162float(h2)),
                                      __float2bfloat16(v3 - __bfloat162float(h3))};
                *reinterpret_cast<__nv_bfloat162*>(sm + HID_HI + row * HID_STRIDE + col * 2) = hp0;
                *reinterpret_cast<__nv_bfloat162*>(sm + HID_LO + row * HID_STRIDE + col * 2) = lp0;
                *reinterpret_cast<__nv_bfloat162*>(sm + HID_HI + (row + 8) * HID_STRIDE + col * 2) = hp1;
                *reinterpret_cast<__nv_bfloat162*>(sm + HID_LO + (row + 8) * HID_STRIDE + col * 2) = lp1;
                acc[mt][nt][0] = acc[mt][nt][1] = acc[mt][nt][2] = acc[mt][nt][3] = 0.f;
            }
        }
    }
    __syncthreads();

    // ===== phase 3: L2 (A from SMEM hidden) =====
    issue_B(W2h, W2l, smb + B_ST(0));
    CP_ASYNC_COMMIT();
    CP_ASYNC_WAIT0();
    __syncthreads();

    for (int t = 0; t < 8; t++) {
        const int cur = t & 1;
        const bool have_next = (t + 1 < 8);
        if (have_next) {
            issue_B(W2h + (size_t)((t + 1) * TBK) * D, W2l + (size_t)((t + 1) * TBK) * D,
                    smb + B_ST((t + 1) & 1));
            CP_ASYNC_COMMIT();
        }
        mma_k16(smb + HID_HI, HID_STRIDE, HID_LO - HID_HI, smb + B_ST(cur), t * 32);
        mma_k16(smb + HID_HI, HID_STRIDE, HID_LO - HID_HI, smb + B_ST(cur), t * 32 + 16);
        if (have_next) { CP_ASYNC_WAIT0(); __syncthreads(); }
    }

    // ===== epilogue: + b2 =====
    {
        const float* b2s = reinterpret_cast<const float*>(sm + 1024);
        #pragma unroll
        for (int mt = 0; mt < 2; mt++) {
            #pragma unroll
            for (int nt = 0; nt < 8; nt++) {
                int row = block_row + wr * 32 + mt * 16 + (lane >> 2);
                int col = wc * 64 + nt * 8 + (lane & 3) * 2;
                float bb0 = b2s[col], bb1 = b2s[col + 1];
                float v0 = acc[mt][nt][0] + bb0, v1 = acc[mt][nt][1] + bb1;
                float v2 = acc[mt][nt][2] + bb0, v3 = acc[mt][nt][3] + bb1;
                if (OutF) {
                    if (row < M)
                        *reinterpret_cast<float2*>(OutF + (size_t)row * D + col) = make_float2(v0, v1);
                    if (row + 8 < M)
                        *reinterpret_cast<float2*>(OutF + (size_t)(row + 8) * D + col) = make_float2(v2, v3);
                }
                if (OutH) {
                    __nv_bfloat16 h0 = __float2bfloat16(v0), h1 = __float2bfloat16(v1);
                    __nv_bfloat16 h2 = __float2bfloat16(v2), h3 = __float2bfloat16(v3);
                    __nv_bfloat162 hp0 = {h0, h1}, hp1 = {h2, h3};
                    __nv_bfloat162 lp0 = {__float2bfloat16(v0 - __bfloat162float(h0)),
                                          __float2bfloat16(v1 - __bfloat162float(h1))};
                    __nv_bfloat162 lp1 = {__float2bfloat16(v2 - __bfloat162float(h2)),
                                          __float2bfloat16(v3 - __bfloat162float(h3))};
                    if (row < M) {
                        *reinterpret_cast<__nv_bfloat162*>(OutH + (size_t)row * D + col) = hp0;
                        *reinterpret_cast<__nv_bfloat162*>(OutL + (size_t)row * D + col) = lp0;
                    }
                    if (row + 8 < M) {
                        *reinterpret_cast<__nv_bfloat162*>(OutH + (size_t)(row + 8) * D + col) = hp1;
                        *reinterpret_cast<__nv_bfloat162*>(OutL + (size_t)(row + 8) * D + col) = lp1;
                    }
                }
            }
        }
    }
}

// ============================================================================
// Edge scatter-add (rows of 256 floats)
// ============================================================================
__global__ void scatter_add_kernel(
    const float4* __restrict__ src, const int* __restrict__ srcIdx,
    const int* __restrict__ dstIdx, float* __restrict__ dst, int E)
{
    long long idx = (long long)blockIdx.x * blockDim.x + threadIdx.x;
    if (idx >= (long long)E * 64) return;
    int e = (int)(idx >> 6);
    int c = (int)(idx & 63);
    float4 v = src[(size_t)srcIdx[e] * 64 + c];
    float* d = dst + ((size_t)dstIdx[e] * (size_t)D + (size_t)c * 4);
    asm volatile("red.global.add.v4.f32 [%0], {%1, %2, %3, %4};"
                 :: "l"(d), "f"(v.x), "f"(v.y), "f"(v.z), "f"(v.w) : "memory");
}

// ============================================================================
// Launcher
// ============================================================================
extern "C" void kernel_launch(void* const* d_in, const int* in_sizes, int n_in,
                              void* d_out, int out_size)
{
    int base = n_in - 24;
    if (base < 0) base = 0;

    const int*   ledge  = (const int*)  d_in[base + 0];
    const int*   cedge  = (const int*)  d_in[base + 1];
    const float* l_emb0 = (const float*)d_in[base + 2];
    const float* c_emb0 = (const float*)d_in[base + 3];

    const int E = in_sizes[base + 0];
    const int L = in_sizes[base + 2] / D;
    const int C = in_sizes[base + 3] / D;

    const float* mlp[5][4];
    for (int m = 0; m < 5; m++)
        for (int p = 0; p < 4; p++)
            mlp[m][p] = (const float*)d_in[base + 4 + m * 4 + p];

    float *lfeat, *cfeat, *laggr, *caggr;
    cudaGetSymbolAddress((void**)&lfeat, g_lfeat);
    cudaGetSymbolAddress((void**)&cfeat, g_cfeat);
    cudaGetSymbolAddress((void**)&laggr, g_laggr);
    cudaGetSymbolAddress((void**)&caggr, g_caggr);
    __nv_bfloat16 *lpre_h, *lpre_l, *cpre_h, *cpre_l;
    __nv_bfloat16 *l2l_h, *l2l_l, *lag_h, *lag_l, *cag_h, *cag_l, *wth, *wtl;
    cudaGetSymbolAddress((void**)&lpre_h, g_lpre_h);
    cudaGetSymbolAddress((void**)&lpre_l, g_lpre_l);
    cudaGetSymbolAddress((void**)&cpre_h, g_cpre_h);
    cudaGetSymbolAddress((void**)&cpre_l, g_cpre_l);
    cudaGetSymbolAddress((void**)&l2l_h,  g_l2l_h);
    cudaGetSymbolAddress((void**)&l2l_l,  g_l2l_l);
    cudaGetSymbolAddress((void**)&lag_h,  g_lag_h);
    cudaGetSymbolAddress((void**)&lag_l,  g_lag_l);
    cudaGetSymbolAddress((void**)&cag_h,  g_cag_h);
    cudaGetSymbolAddress((void**)&cag_l,  g_cag_l);
    cudaGetSymbolAddress((void**)&wth, g_wt_hi);
    cudaGetSymbolAddress((void**)&wtl, g_wt_lo);

    cudaFuncSetAttribute(mlp_fused, cudaFuncAttributeMaxDynamicSharedMemorySize, SMEM_REQ);

    const size_t w1off[5] = {0, 65536, 131072, 196608, 327680};
    const int    w1K [5] = {256, 256, 256, 512, 768};
    const size_t w2off[5] = {524288, 589824, 655360, 720896, 786432};
    for (int m = 0; m < 5; m++) {
        int tot1 = w1K[m] * 256;
        split_kernel<<<(tot1 + 255) / 256, 256>>>(mlp[m][0], wth + w1off[m], wtl + w1off[m], tot1);
        split_kernel<<<(65536 + 255) / 256, 256>>>(mlp[m][2], wth + w2off[m], wtl + w2off[m], 65536);
    }

    float* l_hist = (float*)d_out;
    float* c_hist = l_hist + (size_t)5 * L * D;
    const size_t LD = (size_t)L * D;
    const size_t CD = (size_t)C * D;

    cudaMemcpyAsync(l_hist, l_emb0, LD * sizeof(float), cudaMemcpyDeviceToDevice);
    cudaMemcpyAsync(c_hist, c_emb0, CD * sizeof(float), cudaMemcpyDeviceToDevice);
    split_kernel<<<(int)((LD + 255) / 256), 256>>>(l_emb0, lpre_h, lpre_l, (int)LD);
    split_kernel<<<(int)((CD + 255) / 256), 256>>>(c_emb0, cpre_h, cpre_l, (int)CD);

    const dim3 blk(512);
    const int gL = (L + BM - 1) / BM;
    const int gC = (C + BM - 1) / BM;
    const int sc_blocks = (int)(((long long)E * 64 + 255) / 256);
    const __nv_bfloat16* Z = nullptr;
    float* ZF = nullptr;
    __nv_bfloat16* ZB = nullptr;

    for (int t = 0; t < 4; t++) {
        float* lnew = l_hist + (size_t)(t + 1) * LD;
        float* cnew = c_hist + (size_t)(t + 1) * CD;

        mlp_fused<<<gL, blk, SMEM_REQ>>>(lpre_h, lpre_l, Z, Z, Z, Z,
            wth + w1off[0], wtl + w1off[0], wth + w2off[0], wtl + w2off[0],
            mlp[0][1], mlp[0][3], lfeat, ZB, ZB, L, 1, 0);
        mlp_fused<<<gC, blk, SMEM_REQ>>>(cpre_h, cpre_l, Z, Z, Z, Z,
            wth + w1off[1], wtl + w1off[1], wth + w2off[1], wtl + w2off[1],
            mlp[1][1], mlp[1][3], cfeat, ZB, ZB, C, 1, 0);
        mlp_fused<<<gL, blk, SMEM_REQ>>>(lpre_h, lpre_l, Z, Z, Z, Z,
            wth + w1off[2], wtl + w1off[2], wth + w2off[2], wtl + w2off[2],
            mlp[2][1], mlp[2][3], ZF, l2l_h, l2l_l, L, 1, 1);

        cudaMemsetAsync(caggr, 0, CD * sizeof(float));
        scatter_add_kernel<<<sc_blocks, 256>>>((const float4*)lfeat, ledge, cedge, caggr, E);
        split_kernel<<<(int)((CD + 255) / 256), 256>>>(caggr, cag_h, cag_l, (int)CD);
        mlp_fused<<<gC, blk, SMEM_REQ>>>(cpre_h, cpre_l, cag_h, cag_l, Z, Z,
            wth + w1off[3], wtl + w1off[3], wth + w2off[3], wtl + w2off[3],
            mlp[3][1], mlp[3][3], cnew, cpre_h, cpre_l, C, 2, 0);

        cudaMemsetAsync(laggr, 0, LD * sizeof(float));
        scatter_add_kernel<<<sc_blocks, 256>>>((const float4*)cfeat, cedge, ledge, laggr, E);
        split_kernel<<<(int)((LD + 255) / 256), 256>>>(laggr, lag_h, lag_l, (int)LD);
        mlp_fused<<<gL, blk, SMEM_REQ>>>(lpre_h, lpre_l, lag_h, lag_l, l2l_h, l2l_l,
            wth + w1off[4], wtl + w1off[4], wth + w2off[4], wtl + w2off[4],
            mlp[4][1], mlp[4][3], lnew, lpre_h, lpre_l, L, 3, 0);
    }
}

// round 14
// speedup vs baseline: 2.8957x; 1.0666x over previous
#include <cuda_runtime.h>
#include <cuda_bf16.h>
#include <stdint.h>
#include <stddef.h>

#define D 256
#define LMAX 100000
#define CMAX 50000

// ---- fp32 scratch (scatter sources/sinks only) ----
__device__ float g_lfeat[(size_t)LMAX * D];
__device__ float g_cfeat[(size_t)CMAX * D];
__device__ float g_laggr[(size_t)LMAX * D];
__device__ float g_caggr[(size_t)CMAX * D];

// ---- bf16 hi/lo activation pairs (GEMM A operands) ----
__device__ __nv_bfloat16 g_lpre_h[(size_t)LMAX * D], g_lpre_l[(size_t)LMAX * D];
__device__ __nv_bfloat16 g_cpre_h[(size_t)CMAX * D], g_cpre_l[(size_t)CMAX * D];
__device__ __nv_bfloat16 g_l2l_h [(size_t)LMAX * D], g_l2l_l [(size_t)LMAX * D];
__device__ __nv_bfloat16 g_lag_h [(size_t)LMAX * D], g_lag_l [(size_t)LMAX * D];
__device__ __nv_bfloat16 g_cag_h [(size_t)CMAX * D], g_cag_l [(size_t)CMAX * D];

// ---- bf16 hi/lo split weights, layout preserved [Ktot][256] ----
#define WT_TOTAL 851968
__device__ __nv_bfloat16 g_wt_hi[WT_TOTAL];
__device__ __nv_bfloat16 g_wt_lo[WT_TOTAL];

// ---- base-target PTX helpers ----
__device__ __forceinline__ uint32_t smem_u32(const void* p) {
    uint32_t a;
    asm("{ .reg .u64 t; cvta.to.shared.u64 t, %1; cvt.u32.u64 %0, t; }" : "=r"(a) : "l"(p));
    return a;
}
__device__ __forceinline__ void cp_async16(uint32_t dst, const void* src) {
    asm volatile("cp.async.cg.shared.global [%0], [%1], 16;" :: "r"(dst), "l"(src));
}
#define CP_ASYNC_COMMIT() asm volatile("cp.async.commit_group;" ::: "memory")
#define CP_ASYNC_WAIT0()  asm volatile("cp.async.wait_group 0;" ::: "memory")

#define LDSM4(R, addr)                                                          \
    asm volatile("ldmatrix.sync.aligned.m8n8.x4.shared.b16 {%0,%1,%2,%3}, [%4];" \
        : "=r"((R)[0]), "=r"((R)[1]), "=r"((R)[2]), "=r"((R)[3]) : "r"(addr))
#define LDSM4T(R, addr)                                                         \
    asm volatile("ldmatrix.sync.aligned.m8n8.x4.trans.shared.b16 {%0,%1,%2,%3}, [%4];" \
        : "=r"((R)[0]), "=r"((R)[1]), "=r"((R)[2]), "=r"((R)[3]) : "r"(addr))

#define MMA16816(C, A, B0, B1)                                                  \
    asm volatile("mma.sync.aligned.m16n8k16.row.col.f32.bf16.bf16.f32 "         \
        "{%0,%1,%2,%3}, {%4,%5,%6,%7}, {%8,%9}, {%0,%1,%2,%3};"                 \
        : "+f"((C)[0]), "+f"((C)[1]), "+f"((C)[2]), "+f"((C)[3])                \
        : "r"((A)[0]), "r"((A)[1]), "r"((A)[2]), "r"((A)[3]), "r"(B0), "r"(B1))

// ============================================================================
// Single weight-prep kernel: all 10 matrices fp32 -> bf16 hi/lo in one launch
// ============================================================================
__global__ void prep_weights_kernel(
    const float* __restrict__ s0, const float* __restrict__ s1,
    const float* __restrict__ s2, const float* __restrict__ s3,
    const float* __restrict__ s4, const float* __restrict__ s5,
    const float* __restrict__ s6, const float* __restrict__ s7,
    const float* __restrict__ s8, const float* __restrict__ s9,
    __nv_bfloat16* __restrict__ hi, __nv_bfloat16* __restrict__ lo)
{
    int gid = blockIdx.x * blockDim.x + threadIdx.x;
    if (gid >= WT_TOTAL) return;
    // segment starts (elements): W1 x5 then W2 x5
    const float* src;
    int off;
    if      (gid < 65536)  { src = s0; off = 0; }
    else if (gid < 131072) { src = s1; off = 65536; }
    else if (gid < 196608) { src = s2; off = 131072; }
    else if (gid < 327680) { src = s3; off = 196608; }
    else if (gid < 524288) { src = s4; off = 327680; }
    else if (gid < 589824) { src = s5; off = 524288; }
    else if (gid < 655360) { src = s6; off = 589824; }
    else if (gid < 720896) { src = s7; off = 655360; }
    else if (gid < 786432) { src = s8; off = 720896; }
    else                   { src = s9; off = 786432; }
    float x = src[gid - off];
    __nv_bfloat16 h = __float2bfloat16(x);
    hi[gid] = h;
    lo[gid] = __float2bfloat16(x - __bfloat162float(h));
}

// ============================================================================
// init split: emb fp32 -> hist copy + bf16 hi/lo
// ============================================================================
__global__ void split_init_kernel(const float* __restrict__ src,
                                  float* __restrict__ hist,
                                  __nv_bfloat16* __restrict__ hi,
                                  __nv_bfloat16* __restrict__ lo, int total) {
    int idx = blockIdx.x * blockDim.x + threadIdx.x;
    if (idx >= total) return;
    float x = src[idx];
    hist[idx] = x;
    __nv_bfloat16 h = __float2bfloat16(x);
    hi[idx] = h;
    lo[idx] = __float2bfloat16(x - __bfloat162float(h));
}

// ============================================================================
// aggr split: fp32 -> bf16 hi/lo
// ============================================================================
__global__ void split_kernel(const float* __restrict__ W,
                             __nv_bfloat16* __restrict__ hi,
                             __nv_bfloat16* __restrict__ lo, int total) {
    int idx = blockIdx.x * blockDim.x + threadIdx.x;
    if (idx >= total) return;
    float x = W[idx];
    __nv_bfloat16 h = __float2bfloat16(x);
    hi[idx] = h;
    lo[idx] = __float2bfloat16(x - __bfloat162float(h));
}

// ============================================================================
// Fused 2-layer MLP, 3-term bf16 split HMMA.
// CTA = 64 rows x 256 cols; 256 threads, 8 warps (2x4), warp tile 32x64.
// BK=16 double-buffered; hidden in SMEM; 112 KB/CTA -> 2 CTAs/SM.
// SMEM map:
//   [0,1024) b1   [1024,2048) b2
//   [2048,34816)  B stages: 2 x { hi 8192 | lo 8192 }
//   [34816,47104) A stages: 2 x { hi 3072 | lo 3072 } (48B rows)
//   [47104,114688) hidden hi/lo planes (528B rows)
// ============================================================================
#define BM 64
#define TBK 16
#define B_ST(st)   (2048 + (st) * 16384)
#define B_LO       8192
#define A_ST(st)   (34816 + (st) * 6144)
#define A_LO       3072
#define A_STRIDE   48
#define HID_HI     47104
#define HID_LO     80896
#define HID_STRIDE 528
#define SMEM_REQ   114688

__global__ __launch_bounds__(256, 2) void mlp_fused(
    const __nv_bfloat16* __restrict__ A0h, const __nv_bfloat16* __restrict__ A0l,
    const __nv_bfloat16* __restrict__ A1h, const __nv_bfloat16* __restrict__ A1l,
    const __nv_bfloat16* __restrict__ A2h, const __nv_bfloat16* __restrict__ A2l,
    const __nv_bfloat16* __restrict__ W1h, const __nv_bfloat16* __restrict__ W1l,
    const __nv_bfloat16* __restrict__ W2h, const __nv_bfloat16* __restrict__ W2l,
    const float* __restrict__ b1, const float* __restrict__ b2,
    float* __restrict__ OutF, __nv_bfloat16* __restrict__ OutH,
    __nv_bfloat16* __restrict__ OutL,
    int M, int nseg, int swap0)
{
    extern __shared__ char sm[];
    const uint32_t smb = smem_u32(sm);
    const int tid  = threadIdx.x;
    const int lane = tid & 31;
    const int wid  = tid >> 5;
    const int wr   = wid & 1;               // 2 row groups of 32
    const int wc   = wid >> 1;              // 4 col groups of 64
    const int block_row = blockIdx.x * BM;

    const __nv_bfloat16* Ah[3] = {A0h, A1h, A2h};
    const __nv_bfloat16* Al[3] = {A0l, A1l, A2l};

    if (tid < 256) {
        reinterpret_cast<float*>(sm)[tid] = b1[tid];
        reinterpret_cast<float*>(sm + 1024)[tid] = b2[tid];
    }

    float acc[2][8][4];
    #pragma unroll
    for (int i = 0; i < 2; i++)
        #pragma unroll
        for (int j = 0; j < 8; j++)
            #pragma unroll
            for (int q = 0; q < 4; q++) acc[i][j][q] = 0.f;

    // B stage: 16 k-rows x 256 n x 2B per plane = 8192 B; 512 16B-chunks/plane.
    auto issue_B = [&](const __nv_bfloat16* Wh_, const __nv_bfloat16* Wl_, uint32_t sb) {
        #pragma unroll
        for (int it = 0; it < 2; it++) {
            int idx = tid + it * 256;           // 0..511
            int k = idx >> 5, cn = idx & 31;
            uint32_t doff = (uint32_t)(k * 512 + ((cn ^ (k & 7)) << 4));
            size_t soff = (size_t)k * D + cn * 8;
            cp_async16(sb + doff, Wh_ + soff);
            cp_async16(sb + B_LO + doff, Wl_ + soff);
        }
    };
    // A stage: 64 rows x 16 k x 2B per plane = 2048 B data in 48B-stride rows.
    // 128 chunks/plane x 2 planes = 256 -> one chunk per thread.
    auto issue_A = [&](int s, int kloc, uint32_t sb) {
        const bool swp = (s == 0) && swap0;
        int plane = tid >> 7;                   // 0 = hi, 1 = lo
        int r = (tid >> 1) & 63;
        int c = tid & 1;
        int row = block_row + r;
        int ar = swp ? (row ^ 1) : row;
        if (ar >= M) ar = M - 1;
        size_t soff = (size_t)ar * D + kloc + c * 8;
        uint32_t dst = sb + (uint32_t)plane * A_LO + (uint32_t)(r * A_STRIDE + c * 16);
        cp_async16(dst, (plane ? Al[s] : Ah[s]) + soff);
    };

    // one k16 MMA step. A hi at abase (+row*astride + kbyte), lo at +alo_delta.
    auto mma_k16 = [&](uint32_t abase, int astride, uint32_t alo_delta,
                       int kbyte, uint32_t bbase) {
        uint32_t ah[2][4], al[2][4];
        #pragma unroll
        for (int mt = 0; mt < 2; mt++) {
            uint32_t aaddr = abase
                + (uint32_t)((wr * 32 + mt * 16 + (lane & 15)) * astride)
                + (uint32_t)(kbyte + (lane >> 4) * 16);
            LDSM4(ah[mt], aaddr);
            LDSM4(al[mt], aaddr + alo_delta);
        }
        int kr = lane & 15;
        uint32_t bh[4][4];
        #pragma unroll
        for (int nt = 0; nt < 4; nt++) {
            int cn = wc * 8 + nt * 2 + (lane >> 4);
            LDSM4T(bh[nt], bbase + (uint32_t)(kr * 512 + ((cn ^ (kr & 7)) << 4)));
        }
        #pragma unroll
        for (int nt = 0; nt < 4; nt++)
            #pragma unroll
            for (int mt = 0; mt < 2; mt++) {
                MMA16816(acc[mt][2*nt],   ah[mt], bh[nt][0], bh[nt][1]);
                MMA16816(acc[mt][2*nt+1], ah[mt], bh[nt][2], bh[nt][3]);
                MMA16816(acc[mt][2*nt],   al[mt], bh[nt][0], bh[nt][1]);
                MMA16816(acc[mt][2*nt+1], al[mt], bh[nt][2], bh[nt][3]);
            }
        uint32_t bl[4][4];
        #pragma unroll
        for (int nt = 0; nt < 4; nt++) {
            int cn = wc * 8 + nt * 2 + (lane >> 4);
            LDSM4T(bl[nt], bbase + B_LO + (uint32_t)(kr * 512 + ((cn ^ (kr & 7)) << 4)));
        }
        #pragma unroll
        for (int nt = 0; nt < 4; nt++)
            #pragma unroll
            for (int mt = 0; mt < 2; mt++) {
                MMA16816(acc[mt][2*nt],   ah[mt], bl[nt][0], bl[nt][1]);
                MMA16816(acc[mt][2*nt+1], ah[mt], bl[nt][2], bl[nt][3]);
            }
    };

    // ===== phase 1: L1 (K = nseg*256, BK=16 -> nseg*16 stages) =====
    const int T1 = nseg * 16;
    issue_A(0, 0, smb + A_ST(0));
    issue_B(W1h, W1l, smb + B_ST(0));
    CP_ASYNC_COMMIT();
    CP_ASYNC_WAIT0();
    __syncthreads();

    for (int t = 0; t < T1; t++) {
        const int cur = t & 1;
        const bool have_next = (t + 1 < T1);
        if (have_next) {
            int tn = t + 1, s = tn >> 4, kloc = (tn & 15) * TBK;
            issue_A(s, kloc, smb + A_ST(tn & 1));
            issue_B(W1h + (size_t)(s * D + kloc) * D, W1l + (size_t)(s * D + kloc) * D,
                    smb + B_ST(tn & 1));
            CP_ASYNC_COMMIT();
        }
        mma_k16(smb + A_ST(cur), A_STRIDE, A_LO, 0, smb + B_ST(cur));
        if (have_next) { CP_ASYNC_WAIT0(); __syncthreads(); }
    }
    __syncthreads();

    // ===== phase 2: bias + relu + split -> SMEM hidden =====
    {
        const float* b1s = reinterpret_cast<const float*>(sm);
        #pragma unroll
        for (int mt = 0; mt < 2; mt++) {
            #pragma unroll
            for (int nt = 0; nt < 8; nt++) {
                int row = wr * 32 + mt * 16 + (lane >> 2);
                int col = wc * 64 + nt * 8 + (lane & 3) * 2;
                float bb0 = b1s[col], bb1 = b1s[col + 1];
                float v0 = fmaxf(acc[mt][nt][0] + bb0, 0.f);
                float v1 = fmaxf(acc[mt][nt][1] + bb1, 0.f);
                float v2 = fmaxf(acc[mt][nt][2] + bb0, 0.f);
                float v3 = fmaxf(acc[mt][nt][3] + bb1, 0.f);
                __nv_bfloat16 h0 = __float2bfloat16(v0), h1 = __float2bfloat16(v1);
                __nv_bfloat16 h2 = __float2bfloat16(v2), h3 = __float2bfloat16(v3);
                __nv_bfloat162 hp0 = {h0, h1}, hp1 = {h2, h3};
                __nv_bfloat162 lp0 = {__float2bfloat16(v0 - __bfloat162float(h0)),
                                      __float2bfloat16(v1 - __bfloat162float(h1))};
                __nv_bfloat162 lp1 = {__float2bfloat16(v2 - __bfloat162float(h2)),
                                      __float2bfloat16(v3 - __bfloat162float(h3))};
                *reinterpret_cast<__nv_bfloat162*>(sm + HID_HI + row * HID_STRIDE + col * 2) = hp0;
                *reinterpret_cast<__nv_bfloat162*>(sm + HID_LO + row * HID_STRIDE + col * 2) = lp0;
                *reinterpret_cast<__nv_bfloat162*>(sm + HID_HI + (row + 8) * HID_STRIDE + col * 2) = hp1;
                *reinterpret_cast<__nv_bfloat162*>(sm + HID_LO + (row + 8) * HID_STRIDE + col * 2) = lp1;
                acc[mt][nt][0] = acc[mt][nt][1] = acc[mt][nt][2] = acc[mt][nt][3] = 0.f;
            }
        }
    }
    __syncthreads();

    // ===== phase 3: L2 (A from SMEM hidden; K=256 -> 16 stages) =====
    issue_B(W2h, W2l, smb + B_ST(0));
    CP_ASYNC_COMMIT();
    CP_ASYNC_WAIT0();
    __syncthreads();

    for (int t = 0; t < 16; t++) {
        const int cur = t & 1;
        const bool have_next = (t + 1 < 16);
        if (have_next) {
            issue_B(W2h + (size_t)((t + 1) * TBK) * D, W2l + (size_t)((t + 1) * TBK) * D,
                    smb + B_ST((t + 1) & 1));
            CP_ASYNC_COMMIT();
        }
        // hidden k-offset: t*16 bf16 = t*32 bytes
        mma_k16(smb + HID_HI, HID_STRIDE, HID_LO - HID_HI, t * 32, smb + B_ST(cur));
        if (have_next) { CP_ASYNC_WAIT0(); __syncthreads(); }
    }

    // ===== epilogue: + b2 =====
    {
        const float* b2s = reinterpret_cast<const float*>(sm + 1024);
        #pragma unroll
        for (int mt = 0; mt < 2; mt++) {
            #pragma unroll
            for (int nt = 0; nt < 8; nt++) {
                int row = block_row + wr * 32 + mt * 16 + (lane >> 2);
                int col = wc * 64 + nt * 8 + (lane & 3) * 2;
                float bb0 = b2s[col], bb1 = b2s[col + 1];
                float v0 = acc[mt][nt][0] + bb0, v1 = acc[mt][nt][1] + bb1;
                float v2 = acc[mt][nt][2] + bb0, v3 = acc[mt][nt][3] + bb1;
                if (OutF) {
                    if (row < M)
                        *reinterpret_cast<float2*>(OutF + (size_t)row * D + col) = make_float2(v0, v1);
                    if (row + 8 < M)
                        *reinterpret_cast<float2*>(OutF + (size_t)(row + 8) * D + col) = make_float2(v2, v3);
                }
                if (OutH) {
                    __nv_bfloat16 h0 = __float2bfloat16(v0), h1 = __float2bfloat16(v1);
                    __nv_bfloat16 h2 = __float2bfloat16(v2), h3 = __float2bfloat16(v3);
                    __nv_bfloat162 hp0 = {h0, h1}, hp1 = {h2, h3};
                    __nv_bfloat162 lp0 = {__float2bfloat16(v0 - __bfloat162float(h0)),
                                          __float2bfloat16(v1 - __bfloat162float(h1))};
                    __nv_bfloat162 lp1 = {__float2bfloat16(v2 - __bfloat162float(h2)),
                                          __float2bfloat16(v3 - __bfloat162float(h3))};
                    if (row < M) {
                        *reinterpret_cast<__nv_bfloat162*>(OutH + (size_t)row * D + col) = hp0;
                        *reinterpret_cast<__nv_bfloat162*>(OutL + (size_t)row * D + col) = lp0;
                    }
                    if (row + 8 < M) {
                        *reinterpret_cast<__nv_bfloat162*>(OutH + (size_t)(row + 8) * D + col) = hp1;
                        *reinterpret_cast<__nv_bfloat162*>(OutL + (size_t)(row + 8) * D + col) = lp1;
                    }
                }
            }
        }
    }
}

// ============================================================================
// Edge scatter-add (rows of 256 floats)
// ============================================================================
__global__ void scatter_add_kernel(
    const float4* __restrict__ src, const int* __restrict__ srcIdx,
    const int* __restrict__ dstIdx, float* __restrict__ dst, int E)
{
    long long idx = (long long)blockIdx.x * blockDim.x + threadIdx.x;
    if (idx >= (long long)E * 64) return;
    int e = (int)(idx >> 6);
    int c = (int)(idx & 63);
    float4 v = src[(size_t)srcIdx[e] * 64 + c];
    float* d = dst + ((size_t)dstIdx[e] * (size_t)D + (size_t)c * 4);
    asm volatile("red.global.add.v4.f32 [%0], {%1, %2, %3, %4};"
                 :: "l"(d), "f"(v.x), "f"(v.y), "f"(v.z), "f"(v.w) : "memory");
}

// ============================================================================
// Launcher
// ============================================================================
extern "C" void kernel_launch(void* const* d_in, const int* in_sizes, int n_in,
                              void* d_out, int out_size)
{
    int base = n_in - 24;
    if (base < 0) base = 0;

    const int*   ledge  = (const int*)  d_in[base + 0];
    const int*   cedge  = (const int*)  d_in[base + 1];
    const float* l_emb0 = (const float*)d_in[base + 2];
    const float* c_emb0 = (const float*)d_in[base + 3];

    const int E = in_sizes[base + 0];
    const int L = in_sizes[base + 2] / D;
    const int C = in_sizes[base + 3] / D;

    const float* mlp[5][4];
    for (int m = 0; m < 5; m++)
        for (int p = 0; p < 4; p++)
            mlp[m][p] = (const float*)d_in[base + 4 + m * 4 + p];

    float *lfeat, *cfeat, *laggr, *caggr;
    cudaGetSymbolAddress((void**)&lfeat, g_lfeat);
    cudaGetSymbolAddress((void**)&cfeat, g_cfeat);
    cudaGetSymbolAddress((void**)&laggr, g_laggr);
    cudaGetSymbolAddress((void**)&caggr, g_caggr);
    __nv_bfloat16 *lpre_h, *lpre_l, *cpre_h, *cpre_l;
    __nv_bfloat16 *l2l_h, *l2l_l, *lag_h, *lag_l, *cag_h, *cag_l, *wth, *wtl;
    cudaGetSymbolAddress((void**)&lpre_h, g_lpre_h);
    cudaGetSymbolAddress((void**)&lpre_l, g_lpre_l);
    cudaGetSymbolAddress((void**)&cpre_h, g_cpre_h);
    cudaGetSymbolAddress((void**)&cpre_l, g_cpre_l);
    cudaGetSymbolAddress((void**)&l2l_h,  g_l2l_h);
    cudaGetSymbolAddress((void**)&l2l_l,  g_l2l_l);
    cudaGetSymbolAddress((void**)&lag_h,  g_lag_h);
    cudaGetSymbolAddress((void**)&lag_l,  g_lag_l);
    cudaGetSymbolAddress((void**)&cag_h,  g_cag_h);
    cudaGetSymbolAddress((void**)&cag_l,  g_cag_l);
    cudaGetSymbolAddress((void**)&wth, g_wt_hi);
    cudaGetSymbolAddress((void**)&wtl, g_wt_lo);

    cudaFuncSetAttribute(mlp_fused, cudaFuncAttributeMaxDynamicSharedMemorySize, SMEM_REQ);

    // offsets into g_wt (elements): W1 x5 (K = 256,256,256,512,768) then W2 x5
    const size_t w1off[5] = {0, 65536, 131072, 196608, 327680};
    const size_t w2off[5] = {524288, 589824, 655360, 720896, 786432};

    // 1 launch: all weight splits
    prep_weights_kernel<<<(WT_TOTAL + 255) / 256, 256>>>(
        mlp[0][0], mlp[1][0], mlp[2][0], mlp[3][0], mlp[4][0],
        mlp[0][2], mlp[1][2], mlp[2][2], mlp[3][2], mlp[4][2], wth, wtl);

    float* l_hist = (float*)d_out;
    float* c_hist = l_hist + (size_t)5 * L * D;
    const size_t LD = (size_t)L * D;
    const size_t CD = (size_t)C * D;

    // init splits double as history copies (launches 2 & 3)
    split_init_kernel<<<(int)((LD + 255) / 256), 256>>>(l_emb0, l_hist, lpre_h, lpre_l, (int)LD);
    split_init_kernel<<<(int)((CD + 255) / 256), 256>>>(c_emb0, c_hist, cpre_h, cpre_l, (int)CD);

    const dim3 blk(256);
    const int gL = (L + BM - 1) / BM;
    const int gC = (C + BM - 1) / BM;
    const int sc_blocks = (int)(((long long)E * 64 + 255) / 256);
    const __nv_bfloat16* Z = nullptr;
    float* ZF = nullptr;
    __nv_bfloat16* ZB = nullptr;

    for (int t = 0; t < 4; t++) {
        float* lnew = l_hist + (size_t)(t + 1) * LD;
        float* cnew = c_hist + (size_t)(t + 1) * CD;

        mlp_fused<<<gL, blk, SMEM_REQ>>>(lpre_h, lpre_l, Z, Z, Z, Z,
            wth + w1off[0], wtl + w1off[0], wth + w2off[0], wtl + w2off[0],
            mlp[0][1], mlp[0][3], lfeat, ZB, ZB, L, 1, 0);
        mlp_fused<<<gC, blk, SMEM_REQ>>>(cpre_h, cpre_l, Z, Z, Z, Z,
            wth + w1off[1], wtl + w1off[1], wth + w2off[1], wtl + w2off[1],
            mlp[1][1], mlp[1][3], cfeat, ZB, ZB, C, 1, 0);
        mlp_fused<<<gL, blk, SMEM_REQ>>>(lpre_h, lpre_l, Z, Z, Z, Z,
            wth + w1off[2], wtl + w1off[2], wth + w2off[2], wtl + w2off[2],
            mlp[2][1], mlp[2][3], ZF, l2l_h, l2l_l, L, 1, 1);

        cudaMemsetAsync(caggr, 0, CD * sizeof(float));
        scatter_add_kernel<<<sc_blocks, 256>>>((const float4*)lfeat, ledge, cedge, caggr, E);
        split_kernel<<<(int)((CD + 255) / 256), 256>>>(caggr, cag_h, cag_l, (int)CD);
        mlp_fused<<<gC, blk, SMEM_REQ>>>(cpre_h, cpre_l, cag_h, cag_l, Z, Z,
            wth + w1off[3], wtl + w1off[3], wth + w2off[3], wtl + w2off[3],
            mlp[3][1], mlp[3][3], cnew, cpre_h, cpre_l, C, 2, 0);

        cudaMemsetAsync(laggr, 0, LD * sizeof(float));
        scatter_add_kernel<<<sc_blocks, 256>>>((const float4*)cfeat, cedge, ledge, laggr, E);
        split_kernel<<<(int)((LD + 255) / 256), 256>>>(laggr, lag_h, lag_l, (int)LD);
        mlp_fused<<<gL, blk, SMEM_REQ>>>(lpre_h, lpre_l, lag_h, lag_l, l2l_h, l2l_l,
            wth + w1off[4], wtl + w1off[4], wth + w2off[4], wtl + w2off[4],
            mlp[4][1], mlp[4][3], lnew, lpre_h, lpre_l, L, 3, 0);
    }
}

// round 16
// speedup vs baseline: 2.9583x; 1.0216x over previous
#include <cuda_runtime.h>
#include <cuda_bf16.h>
#include <stdint.h>
#include <stddef.h>

#define D 256
#define LMAX 100000
#define CMAX 50000

// ---- fp32 scratch (scatter sources/sinks only) ----
__device__ float g_lfeat[(size_t)LMAX * D];
__device__ float g_cfeat[(size_t)CMAX * D];
__device__ float g_laggr[(size_t)LMAX * D];
__device__ float g_caggr[(size_t)CMAX * D];

// ---- bf16 hi/lo activation pairs (GEMM A operands) ----
__device__ __nv_bfloat16 g_lpre_h[(size_t)LMAX * D], g_lpre_l[(size_t)LMAX * D];
__device__ __nv_bfloat16 g_cpre_h[(size_t)CMAX * D], g_cpre_l[(size_t)CMAX * D];
__device__ __nv_bfloat16 g_l2l_h [(size_t)LMAX * D], g_l2l_l [(size_t)LMAX * D];
__device__ __nv_bfloat16 g_lag_h [(size_t)LMAX * D], g_lag_l [(size_t)LMAX * D];
__device__ __nv_bfloat16 g_cag_h [(size_t)CMAX * D], g_cag_l [(size_t)CMAX * D];

// ---- bf16 hi/lo split weights, layout preserved [Ktot][256] ----
#define WT_TOTAL 851968
__device__ __nv_bfloat16 g_wt_hi[WT_TOTAL];
__device__ __nv_bfloat16 g_wt_lo[WT_TOTAL];

// ---- base-target PTX helpers ----
__device__ __forceinline__ uint32_t smem_u32(const void* p) {
    uint32_t a;
    asm("{ .reg .u64 t; cvta.to.shared.u64 t, %1; cvt.u32.u64 %0, t; }" : "=r"(a) : "l"(p));
    return a;
}
__device__ __forceinline__ void cp_async16(uint32_t dst, const void* src) {
    asm volatile("cp.async.cg.shared.global [%0], [%1], 16;" :: "r"(dst), "l"(src));
}
#define CP_ASYNC_COMMIT() asm volatile("cp.async.commit_group;" ::: "memory")
#define CP_ASYNC_WAIT0()  asm volatile("cp.async.wait_group 0;" ::: "memory")
#define CP_ASYNC_WAIT1()  asm volatile("cp.async.wait_group 1;" ::: "memory")

#define LDSM4(R, addr)                                                          \
    asm volatile("ldmatrix.sync.aligned.m8n8.x4.shared.b16 {%0,%1,%2,%3}, [%4];" \
        : "=r"((R)[0]), "=r"((R)[1]), "=r"((R)[2]), "=r"((R)[3]) : "r"(addr))
#define LDSM4T(R, addr)                                                         \
    asm volatile("ldmatrix.sync.aligned.m8n8.x4.trans.shared.b16 {%0,%1,%2,%3}, [%4];" \
        : "=r"((R)[0]), "=r"((R)[1]), "=r"((R)[2]), "=r"((R)[3]) : "r"(addr))

#define MMA16816(C, A, B0, B1)                                                  \
    asm volatile("mma.sync.aligned.m16n8k16.row.col.f32.bf16.bf16.f32 "         \
        "{%0,%1,%2,%3}, {%4,%5,%6,%7}, {%8,%9}, {%0,%1,%2,%3};"                 \
        : "+f"((C)[0]), "+f"((C)[1]), "+f"((C)[2]), "+f"((C)[3])                \
        : "r"((A)[0]), "r"((A)[1]), "r"((A)[2]), "r"((A)[3]), "r"(B0), "r"(B1))

// ============================================================================
// Single weight-prep kernel
// ============================================================================
__global__ void prep_weights_kernel(
    const float* __restrict__ s0, const float* __restrict__ s1,
    const float* __restrict__ s2, const float* __restrict__ s3,
    const float* __restrict__ s4, const float* __restrict__ s5,
    const float* __restrict__ s6, const float* __restrict__ s7,
    const float* __restrict__ s8, const float* __restrict__ s9,
    __nv_bfloat16* __restrict__ hi, __nv_bfloat16* __restrict__ lo)
{
    int gid = blockIdx.x * blockDim.x + threadIdx.x;
    if (gid >= WT_TOTAL) return;
    const float* src;
    int off;
    if      (gid < 65536)  { src = s0; off = 0; }
    else if (gid < 131072) { src = s1; off = 65536; }
    else if (gid < 196608) { src = s2; off = 131072; }
    else if (gid < 327680) { src = s3; off = 196608; }
    else if (gid < 524288) { src = s4; off = 327680; }
    else if (gid < 589824) { src = s5; off = 524288; }
    else if (gid < 655360) { src = s6; off = 589824; }
    else if (gid < 720896) { src = s7; off = 655360; }
    else if (gid < 786432) { src = s8; off = 720896; }
    else                   { src = s9; off = 786432; }
    float x = src[gid - off];
    __nv_bfloat16 h = __float2bfloat16(x);
    hi[gid] = h;
    lo[gid] = __float2bfloat16(x - __bfloat162float(h));
}

// ============================================================================
// init split: emb fp32 -> hist copy + bf16 hi/lo
// ============================================================================
__global__ void split_init_kernel(const float* __restrict__ src,
                                  float* __restrict__ hist,
                                  __nv_bfloat16* __restrict__ hi,
                                  __nv_bfloat16* __restrict__ lo, int total) {
    int idx = blockIdx.x * blockDim.x + threadIdx.x;
    if (idx >= total) return;
    float x = src[idx];
    hist[idx] = x;
    __nv_bfloat16 h = __float2bfloat16(x);
    hi[idx] = h;
    lo[idx] = __float2bfloat16(x - __bfloat162float(h));
}

// ============================================================================
// aggr split: fp32 -> bf16 hi/lo
// ============================================================================
__global__ void split_kernel(const float* __restrict__ W,
                             __nv_bfloat16* __restrict__ hi,
                             __nv_bfloat16* __restrict__ lo, int total) {
    int idx = blockIdx.x * blockDim.x + threadIdx.x;
    if (idx >= total) return;
    float x = W[idx];
    __nv_bfloat16 h = __float2bfloat16(x);
    hi[idx] = h;
    lo[idx] = __float2bfloat16(x - __bfloat162float(h));
}

// ============================================================================
// Fused 2-layer MLP, 3-term bf16 split HMMA.
// CTA = 64 rows x 256 cols; 256 threads, 8 warps (2x4), warp tile 32x64.
// Phase 1: 3-stage cp.async pipeline (wait_group 1).
// Phase 3: hidden-in-SMEM A, 2-stage B with B0 prefetched during phase 2.
// 112 KB/CTA -> 2 CTAs/SM via phase-disjoint SMEM overlays:
//   [0,2048)       b1,b2
//   [2048,34816)   B3 phase-3 stages: 2 x { hi 8192 | lo 8192 }
//   [34816,53248)  A stages (phase 1 only): 3 x { hi 3072 | lo 3072 }
//   [53248,102400) B1 stages (phase 1 only): 3 x { hi 8192 | lo 8192 }
//   [47104,114688) hidden hi/lo planes (phase 2/3 only; overlays A/B1)
// ============================================================================
#define BM 64
#define TBK 16
#define B3_ST(st)  (2048 + (st) * 16384)
#define A_ST(st)   (34816 + (st) * 6144)
#define B1_ST(st)  (53248 + (st) * 16384)
#define B_LO       8192
#define A_LO       3072
#define A_STRIDE   48
#define HID_HI     47104
#define HID_LO     80896
#define HID_STRIDE 528
#define SMEM_REQ   114688

__global__ __launch_bounds__(256, 2) void mlp_fused(
    const __nv_bfloat16* __restrict__ A0h, const __nv_bfloat16* __restrict__ A0l,
    const __nv_bfloat16* __restrict__ A1h, const __nv_bfloat16* __restrict__ A1l,
    const __nv_bfloat16* __restrict__ A2h, const __nv_bfloat16* __restrict__ A2l,
    const __nv_bfloat16* __restrict__ W1h, const __nv_bfloat16* __restrict__ W1l,
    const __nv_bfloat16* __restrict__ W2h, const __nv_bfloat16* __restrict__ W2l,
    const float* __restrict__ b1, const float* __restrict__ b2,
    float* __restrict__ OutF, __nv_bfloat16* __restrict__ OutH,
    __nv_bfloat16* __restrict__ OutL,
    int M, int nseg, int swap0)
{
    extern __shared__ char sm[];
    const uint32_t smb = smem_u32(sm);
    const int tid  = threadIdx.x;
    const int lane = tid & 31;
    const int wid  = tid >> 5;
    const int wr   = wid & 1;
    const int wc   = wid >> 1;
    const int block_row = blockIdx.x * BM;

    const __nv_bfloat16* Ah[3] = {A0h, A1h, A2h};
    const __nv_bfloat16* Al[3] = {A0l, A1l, A2l};

    if (tid < 256) {
        reinterpret_cast<float*>(sm)[tid] = b1[tid];
        reinterpret_cast<float*>(sm + 1024)[tid] = b2[tid];
    }

    float acc[2][8][4];
    #pragma unroll
    for (int i = 0; i < 2; i++)
        #pragma unroll
        for (int j = 0; j < 8; j++)
            #pragma unroll
            for (int q = 0; q < 4; q++) acc[i][j][q] = 0.f;

    auto issue_B = [&](const __nv_bfloat16* Wh_, const __nv_bfloat16* Wl_, uint32_t sb) {
        #pragma unroll
        for (int it = 0; it < 2; it++) {
            int idx = tid + it * 256;
            int k = idx >> 5, cn = idx & 31;
            uint32_t doff = (uint32_t)(k * 512 + ((cn ^ (k & 7)) << 4));
            size_t soff = (size_t)k * D + cn * 8;
            cp_async16(sb + doff, Wh_ + soff);
            cp_async16(sb + B_LO + doff, Wl_ + soff);
        }
    };
    auto issue_A = [&](int s, int kloc, uint32_t sb) {
        const bool swp = (s == 0) && swap0;
        int plane = tid >> 7;
        int r = (tid >> 1) & 63;
        int c = tid & 1;
        int row = block_row + r;
        int ar = swp ? (row ^ 1) : row;
        if (ar >= M) ar = M - 1;
        size_t soff = (size_t)ar * D + kloc + c * 8;
        uint32_t dst = sb + (uint32_t)plane * A_LO + (uint32_t)(r * A_STRIDE + c * 16);
        cp_async16(dst, (plane ? Al[s] : Ah[s]) + soff);
    };

    auto mma_k16 = [&](uint32_t abase, int astride, uint32_t alo_delta,
                       int kbyte, uint32_t bbase) {
        uint32_t ah[2][4], al[2][4];
        #pragma unroll
        for (int mt = 0; mt < 2; mt++) {
            uint32_t aaddr = abase
                + (uint32_t)((wr * 32 + mt * 16 + (lane & 15)) * astride)
                + (uint32_t)(kbyte + (lane >> 4) * 16);
            LDSM4(ah[mt], aaddr);
            LDSM4(al[mt], aaddr + alo_delta);
        }
        int kr = lane & 15;
        uint32_t bh[4][4];
        #pragma unroll
        for (int nt = 0; nt < 4; nt++) {
            int cn = wc * 8 + nt * 2 + (lane >> 4);
            LDSM4T(bh[nt], bbase + (uint32_t)(kr * 512 + ((cn ^ (kr & 7)) << 4)));
        }
        #pragma unroll
        for (int nt = 0; nt < 4; nt++)
            #pragma unroll
            for (int mt = 0; mt < 2; mt++) {
                MMA16816(acc[mt][2*nt],   ah[mt], bh[nt][0], bh[nt][1]);
                MMA16816(acc[mt][2*nt+1], ah[mt], bh[nt][2], bh[nt][3]);
                MMA16816(acc[mt][2*nt],   al[mt], bh[nt][0], bh[nt][1]);
                MMA16816(acc[mt][2*nt+1], al[mt], bh[nt][2], bh[nt][3]);
            }
        uint32_t bl[4][4];
        #pragma unroll
        for (int nt = 0; nt < 4; nt++) {
            int cn = wc * 8 + nt * 2 + (lane >> 4);
            LDSM4T(bl[nt], bbase + B_LO + (uint32_t)(kr * 512 + ((cn ^ (kr & 7)) << 4)));
        }
        #pragma unroll
        for (int nt = 0; nt < 4; nt++)
            #pragma unroll
            for (int mt = 0; mt < 2; mt++) {
                MMA16816(acc[mt][2*nt],   ah[mt], bl[nt][0], bl[nt][1]);
                MMA16816(acc[mt][2*nt+1], ah[mt], bl[nt][2], bl[nt][3]);
            }
    };

    // ===== phase 1: L1, 3-stage pipeline =====
    // Group discipline: prologue commits stage0, stage1. Loop iter t commits
    // exactly one group (stage t+2 or empty). wait_group 1 at iter end =>
    // stage t+1 resident before iter t+1's compute.
    const int T1 = nseg * 16;
    issue_A(0, 0, smb + A_ST(0));
    issue_B(W1h, W1l, smb + B1_ST(0));
    CP_ASYNC_COMMIT();
    if (T1 > 1) {
        issue_A(0, TBK, smb + A_ST(1));
        issue_B(W1h + (size_t)TBK * D, W1l + (size_t)TBK * D, smb + B1_ST(1));
    }
    CP_ASYNC_COMMIT();
    CP_ASYNC_WAIT1();
    __syncthreads();

    for (int t = 0; t < T1; t++) {
        int tn = t + 2;
        if (tn < T1) {
            int s = tn >> 4, kloc = (tn & 15) * TBK;
            issue_A(s, kloc, smb + A_ST(tn % 3));
            issue_B(W1h + (size_t)(s * D + kloc) * D, W1l + (size_t)(s * D + kloc) * D,
                    smb + B1_ST(tn % 3));
        }
        CP_ASYNC_COMMIT();
        mma_k16(smb + A_ST(t % 3), A_STRIDE, A_LO, 0, smb + B1_ST(t % 3));
        CP_ASYNC_WAIT1();
        __syncthreads();
    }

    // prefetch phase-3 B stage 0 (disjoint region) -> overlaps phase 2
    issue_B(W2h, W2l, smb + B3_ST(0));
    CP_ASYNC_COMMIT();

    // ===== phase 2: bias + relu + split -> SMEM hidden =====
    {
        const float* b1s = reinterpret_cast<const float*>(sm);
        #pragma unroll
        for (int mt = 0; mt < 2; mt++) {
            #pragma unroll
            for (int nt = 0; nt < 8; nt++) {
                int row = wr * 32 + mt * 16 + (lane >> 2);
                int col = wc * 64 + nt * 8 + (lane & 3) * 2;
                float bb0 = b1s[col], bb1 = b1s[col + 1];
                float v0 = fmaxf(acc[mt][nt][0] + bb0, 0.f);
                float v1 = fmaxf(acc[mt][nt][1] + bb1, 0.f);
                float v2 = fmaxf(acc[mt][nt][2] + bb0, 0.f);
                float v3 = fmaxf(acc[mt][nt][3] + bb1, 0.f);
                __nv_bfloat16 h0 = __float2bfloat16(v0), h1 = __float2bfloat16(v1);
                __nv_bfloat16 h2 = __float2bfloat16(v2), h3 = __float2bfloat16(v3);
                __nv_bfloat162 hp0 = {h0, h1}, hp1 = {h2, h3};
                __nv_bfloat162 lp0 = {__float2bfloat16(v0 - __bfloat162float(h0)),
                                      __float2bfloat16(v1 - __bfloat162float(h1))};
                __nv_bfloat162 lp1 = {__float2bfloat16(v2 - __bfloat162float(h2)),
                                      __float2bfloat16(v3 - __bfloat162float(h3))};
                *reinterpret_cast<__nv_bfloat162*>(sm + HID_HI + row * HID_STRIDE + col * 2) = hp0;
                *reinterpret_cast<__nv_bfloat162*>(sm + HID_LO + row * HID_STRIDE + col * 2) = lp0;
                *reinterpret_cast<__nv_bfloat162*>(sm + HID_HI + (row + 8) * HID_STRIDE + col * 2) = hp1;
                *reinterpret_cast<__nv_bfloat162*>(sm + HID_LO + (row + 8) * HID_STRIDE + col * 2) = lp1;
                acc[mt][nt][0] = acc[mt][nt][1] = acc[mt][nt][2] = acc[mt][nt][3] = 0.f;
            }
        }
    }
    __syncthreads();      // hidden visible to all warps
    CP_ASYNC_WAIT0();     // my B3_0 chunks landed
    __syncthreads();      // everyone's B3_0 chunks visible

    // ===== phase 3: L2 (A from SMEM hidden; 16 stages, B double-buffered) =====
    for (int t = 0; t < 16; t++) {
        const bool have_next = (t + 1 < 16);
        if (have_next) {
            issue_B(W2h + (size_t)((t + 1) * TBK) * D, W2l + (size_t)((t + 1) * TBK) * D,
                    smb + B3_ST((t + 1) & 1));
            CP_ASYNC_COMMIT();
        }
        mma_k16(smb + HID_HI, HID_STRIDE, HID_LO - HID_HI, t * 32, smb + B3_ST(t & 1));
        if (have_next) { CP_ASYNC_WAIT0(); __syncthreads(); }
    }

    // ===== epilogue: + b2 =====
    {
        const float* b2s = reinterpret_cast<const float*>(sm + 1024);
        #pragma unroll
        for (int mt = 0; mt < 2; mt++) {
            #pragma unroll
            for (int nt = 0; nt < 8; nt++) {
                int row = block_row + wr * 32 + mt * 16 + (lane >> 2);
                int col = wc * 64 + nt * 8 + (lane & 3) * 2;
                float bb0 = b2s[col], bb1 = b2s[col + 1];
                float v0 = acc[mt][nt][0] + bb0, v1 = acc[mt][nt][1] + bb1;
                float v2 = acc[mt][nt][2] + bb0, v3 = acc[mt][nt][3] + bb1;
                if (OutF) {
                    if (row < M)
                        *reinterpret_cast<float2*>(OutF + (size_t)row * D + col) = make_float2(v0, v1);
                    if (row + 8 < M)
                        *reinterpret_cast<float2*>(OutF + (size_t)(row + 8) * D + col) = make_float2(v2, v3);
                }
                if (OutH) {
                    __nv_bfloat16 h0 = __float2bfloat16(v0), h1 = __float2bfloat16(v1);
                    __nv_bfloat16 h2 = __float2bfloat16(v2), h3 = __float2bfloat16(v3);
                    __nv_bfloat162 hp0 = {h0, h1}, hp1 = {h2, h3};
                    __nv_bfloat162 lp0 = {__float2bfloat16(v0 - __bfloat162float(h0)),
                                          __float2bfloat16(v1 - __bfloat162float(h1))};
                    __nv_bfloat162 lp1 = {__float2bfloat16(v2 - __bfloat162float(h2)),
                                          __float2bfloat16(v3 - __bfloat162float(h3))};
                    if (row < M) {
                        *reinterpret_cast<__nv_bfloat162*>(OutH + (size_t)row * D + col) = hp0;
                        *reinterpret_cast<__nv_bfloat162*>(OutL + (size_t)row * D + col) = lp0;
                    }
                    if (row + 8 < M) {
                        *reinterpret_cast<__nv_bfloat162*>(OutH + (size_t)(row + 8) * D + col) = hp1;
                        *reinterpret_cast<__nv_bfloat162*>(OutL + (size_t)(row + 8) * D + col) = lp1;
                    }
                }
            }
        }
    }
}

// ============================================================================
// Edge scatter-add (rows of 256 floats)
// ============================================================================
__global__ void scatter_add_kernel(
    const float4* __restrict__ src, const int* __restrict__ srcIdx,
    const int* __restrict__ dstIdx, float* __restrict__ dst, int E)
{
    long long idx = (long long)blockIdx.x * blockDim.x + threadIdx.x;
    if (idx >= (long long)E * 64) return;
    int e = (int)(idx >> 6);
    int c = (int)(idx & 63);
    float4 v = src[(size_t)srcIdx[e] * 64 + c];
    float* d = dst + ((size_t)dstIdx[e] * (size_t)D + (size_t)c * 4);
    asm volatile("red.global.add.v4.f32 [%0], {%1, %2, %3, %4};"
                 :: "l"(d), "f"(v.x), "f"(v.y), "f"(v.z), "f"(v.w) : "memory");
}

// ============================================================================
// Launcher
// ============================================================================
extern "C" void kernel_launch(void* const* d_in, const int* in_sizes, int n_in,
                              void* d_out, int out_size)
{
    int base = n_in - 24;
    if (base < 0) base = 0;

    const int*   ledge  = (const int*)  d_in[base + 0];
    const int*   cedge  = (const int*)  d_in[base + 1];
    const float* l_emb0 = (const float*)d_in[base + 2];
    const float* c_emb0 = (const float*)d_in[base + 3];

    const int E = in_sizes[base + 0];
    const int L = in_sizes[base + 2] / D;
    const int C = in_sizes[base + 3] / D;

    const float* mlp[5][4];
    for (int m = 0; m < 5; m++)
        for (int p = 0; p < 4; p++)
            mlp[m][p] = (const float*)d_in[base + 4 + m * 4 + p];

    float *lfeat, *cfeat, *laggr, *caggr;
    cudaGetSymbolAddress((void**)&lfeat, g_lfeat);
    cudaGetSymbolAddress((void**)&cfeat, g_cfeat);
    cudaGetSymbolAddress((void**)&laggr, g_laggr);
    cudaGetSymbolAddress((void**)&caggr, g_caggr);
    __nv_bfloat16 *lpre_h, *lpre_l, *cpre_h, *cpre_l;
    __nv_bfloat16 *l2l_h, *l2l_l, *lag_h, *lag_l, *cag_h, *cag_l, *wth, *wtl;
    cudaGetSymbolAddress((void**)&lpre_h, g_lpre_h);
    cudaGetSymbolAddress((void**)&lpre_l, g_lpre_l);
    cudaGetSymbolAddress((void**)&cpre_h, g_cpre_h);
    cudaGetSymbolAddress((void**)&cpre_l, g_cpre_l);
    cudaGetSymbolAddress((void**)&l2l_h,  g_l2l_h);
    cudaGetSymbolAddress((void**)&l2l_l,  g_l2l_l);
    cudaGetSymbolAddress((void**)&lag_h,  g_lag_h);
    cudaGetSymbolAddress((void**)&lag_l,  g_lag_l);
    cudaGetSymbolAddress((void**)&cag_h,  g_cag_h);
    cudaGetSymbolAddress((void**)&cag_l,  g_cag_l);
    cudaGetSymbolAddress((void**)&wth, g_wt_hi);
    cudaGetSymbolAddress((void**)&wtl, g_wt_lo);

    cudaFuncSetAttribute(mlp_fused, cudaFuncAttributeMaxDynamicSharedMemorySize, SMEM_REQ);

    const size_t w1off[5] = {0, 65536, 131072, 196608, 327680};
    const size_t w2off[5] = {524288, 589824, 655360, 720896, 786432};

    prep_weights_kernel<<<(WT_TOTAL + 255) / 256, 256>>>(
        mlp[0][0], mlp[1][0], mlp[2][0], mlp[3][0], mlp[4][0],
        mlp[0][2], mlp[1][2], mlp[2][2], mlp[3][2], mlp[4][2], wth, wtl);

    float* l_hist = (float*)d_out;
    float* c_hist = l_hist + (size_t)5 * L * D;
    const size_t LD = (size_t)L * D;
    const size_t CD = (size_t)C * D;

    split_init_kernel<<<(int)((LD + 255) / 256), 256>>>(l_emb0, l_hist, lpre_h, lpre_l, (int)LD);
    split_init_kernel<<<(int)((CD + 255) / 256), 256>>>(c_emb0, c_hist, cpre_h, cpre_l, (int)CD);

    const dim3 blk(256);
    const int gL = (L + BM - 1) / BM;
    const int gC = (C + BM - 1) / BM;
    const int sc_blocks = (int)(((long long)E * 64 + 255) / 256);
    const __nv_bfloat16* Z = nullptr;
    float* ZF = nullptr;
    __nv_bfloat16* ZB = nullptr;

    for (int t = 0; t < 4; t++) {
        float* lnew = l_hist + (size_t)(t + 1) * LD;
        float* cnew = c_hist + (size_t)(t + 1) * CD;

        mlp_fused<<<gL, blk, SMEM_REQ>>>(lpre_h, lpre_l, Z, Z, Z, Z,
            wth + w1off[0], wtl + w1off[0], wth + w2off[0], wtl + w2off[0],
            mlp[0][1], mlp[0][3], lfeat, ZB, ZB, L, 1, 0);
        mlp_fused<<<gC, blk, SMEM_REQ>>>(cpre_h, cpre_l, Z, Z, Z, Z,
            wth + w1off[1], wtl + w1off[1], wth + w2off[1], wtl + w2off[1],
            mlp[1][1], mlp[1][3], cfeat, ZB, ZB, C, 1, 0);
        mlp_fused<<<gL, blk, SMEM_REQ>>>(lpre_h, lpre_l, Z, Z, Z, Z,
            wth + w1off[2], wtl + w1off[2], wth + w2off[2], wtl + w2off[2],
            mlp[2][1], mlp[2][3], ZF, l2l_h, l2l_l, L, 1, 1);

        cudaMemsetAsync(caggr, 0, CD * sizeof(float));
        scatter_add_kernel<<<sc_blocks, 256>>>((const float4*)lfeat, ledge, cedge, caggr, E);
        split_kernel<<<(int)((CD + 255) / 256), 256>>>(caggr, cag_h, cag_l, (int)CD);
        mlp_fused<<<gC, blk, SMEM_REQ>>>(cpre_h, cpre_l, cag_h, cag_l, Z, Z,
            wth + w1off[3], wtl + w1off[3], wth + w2off[3], wtl + w2off[3],
            mlp[3][1], mlp[3][3], cnew, cpre_h, cpre_l, C, 2, 0);

        cudaMemsetAsync(laggr, 0, LD * sizeof(float));
        scatter_add_kernel<<<sc_blocks, 256>>>((const float4*)cfeat, cedge, ledge, laggr, E);
        split_kernel<<<(int)((LD + 255) / 256), 256>>>(laggr, lag_h, lag_l, (int)LD);
        mlp_fused<<<gL, blk, SMEM_REQ>>>(lpre_h, lpre_l, lag_h, lag_l, l2l_h, l2l_l,
            wth + w1off[4], wtl + w1off[4], wth + w2off[4], wtl + w2off[4],
            mlp[4][1], mlp[4][3], lnew, lpre_h, lpre_l, L, 3, 0);
    }
}